// round 6
// baseline (speedup 1.0000x reference)
#include <cuda_runtime.h>
#include <math.h>
#include <stddef.h>
#include <stdint.h>

#define D_MODEL 768
#define NHEAD 12
#define DK 64
#define FF 3072
#define NB 2
#define NL 1024
#define MTOT (NB*NL)   // 2048

// ---------------- scratch ----------------
#define OFF_Q    0
#define OFF_K    1572864
#define OFF_V    3145728
#define OFF_BIAS 4718592
#define OFF_AO   29884416
#define OFF_X1   31457280
#define OFF_X    33030144
#define OFF_H    34603008
#define OFF_X2   40894464
#define OFF_PART 42467328
#define SCRATCH_TOTAL (42467328 + 8*1572864)

__device__ float g_scratch[SCRATCH_TOTAL];

#define BM 128
#define BN 128

#define MODE_QKV 0
#define MODE_BIAS_RES 1
#define MODE_BIAS_RELU 2
#define MODE_PART 3

__device__ __forceinline__ uint32_t f2tf32(float x) {
    uint32_t r;
    asm("cvt.rna.tf32.f32 %0, %1;" : "=r"(r) : "f"(x));
    return r;
}
__device__ __forceinline__ float tf32f(float x) {
    return __uint_as_float(f2tf32(x));
}
__device__ __forceinline__ void mma_tf32(float* c, const uint32_t* a, const uint32_t* b) {
    asm volatile("mma.sync.aligned.m16n8k8.row.col.f32.tf32.tf32.f32 "
        "{%0,%1,%2,%3}, {%4,%5,%6,%7}, {%8,%9}, {%0,%1,%2,%3};"
        : "+f"(c[0]), "+f"(c[1]), "+f"(c[2]), "+f"(c[3])
        : "r"(a[0]), "r"(a[1]), "r"(a[2]), "r"(a[3]), "r"(b[0]), "r"(b[1]));
}

// ---------------- tensor-core GEMM: 128x128x16 tiles, tf32 mma.sync ----------------
#define SMS 136
#define ABUF 2176
#define BBASE 4352

template<int MODE>
__global__ __launch_bounds__(256, 2)
void tgemm_kernel(const float* __restrict__ A,
                  const float* __restrict__ B0, const float* __restrict__ B1, const float* __restrict__ B2,
                  const float* __restrict__ bias0, const float* __restrict__ bias1, const float* __restrict__ bias2,
                  const float* __restrict__ R,
                  float* __restrict__ C0, float* __restrict__ C1, float* __restrict__ C2,
                  int M, int N, int K, int lda)
{
    __shared__ float smem[2 * ABUF + 2 * ABUF];

    const int bx = blockIdx.x, by = blockIdx.y;
    const int tid = threadIdx.x;

    const float* Asrc = A;
    const float* Bsel = B0;
    const float* bsel = bias0;
    size_t outoff = 0;
    int ncol0 = bx * BN;
    int Nw = N;
    int region = 0;
    if (MODE == MODE_QKV) {
        region = ncol0 / 768;
        Bsel = (region == 0) ? B0 : (region == 1 ? B1 : B2);
        bsel = (region == 0) ? bias0 : (region == 1 ? bias1 : bias2);
        ncol0 -= region * 768;
        Nw = 768;
    }
    if (MODE == MODE_PART) {
        const int z = blockIdx.z;
        Asrc = A + (size_t)z * K;
        Bsel = B0 + (size_t)z * K * N;
        outoff = (size_t)z * ((size_t)M * N);
    }

    const int rA = tid >> 1, cA = (tid & 1) * 8;
    const int rB = tid >> 4, cB = (tid & 15) * 8;
    const float* Ap = Asrc + (size_t)(by * BM + rA) * lda + cA;
    const float* Bp = Bsel + (size_t)rB * Nw + ncol0 + cB;

    const int lane = tid & 31, warp = tid >> 5;
    const int wm = warp >> 1, wn = warp & 1;
    const int frow = lane >> 2, fcol = lane & 3;

    float acc[2][8][4];
    #pragma unroll
    for (int i = 0; i < 2; i++)
        #pragma unroll
        for (int j = 0; j < 8; j++)
            #pragma unroll
            for (int r = 0; r < 4; r++) acc[i][j][r] = 0.0f;

    const int NK = K / 16;

    float4 la0 = *(const float4*)Ap, la1 = *(const float4*)(Ap + 4);
    float4 lb0 = *(const float4*)Bp, lb1 = *(const float4*)(Bp + 4);
    Ap += 16; Bp += (size_t)16 * Nw;
    {
        float* Ad = smem;
        float* Bd = smem + BBASE;
        float va[8] = {la0.x, la0.y, la0.z, la0.w, la1.x, la1.y, la1.z, la1.w};
        #pragma unroll
        for (int j = 0; j < 8; j++) Ad[(cA + j) * SMS + rA] = tf32f(va[j]);
        float4 v0 = make_float4(tf32f(lb0.x), tf32f(lb0.y), tf32f(lb0.z), tf32f(lb0.w));
        float4 v1 = make_float4(tf32f(lb1.x), tf32f(lb1.y), tf32f(lb1.z), tf32f(lb1.w));
        *(float4*)&Bd[rB * SMS + cB]     = v0;
        *(float4*)&Bd[rB * SMS + cB + 4] = v1;
    }
    __syncthreads();

    int buf = 0;
    for (int kt = 0; kt < NK; kt++) {
        float4 na0, na1, nb0, nb1;
        const bool more = (kt + 1 < NK);
        if (more) {
            na0 = *(const float4*)Ap; na1 = *(const float4*)(Ap + 4);
            nb0 = *(const float4*)Bp; nb1 = *(const float4*)(Bp + 4);
            Ap += 16; Bp += (size_t)16 * Nw;
        }

        const float* As_ = smem + buf * ABUF;
        const float* Bs_ = smem + BBASE + buf * ABUF;

        #pragma unroll
        for (int ks = 0; ks < 2; ks++) {
            const int kb = ks * 8;
            uint32_t aF[2][4], bF[8][2];
            #pragma unroll
            for (int mt = 0; mt < 2; mt++) {
                const int m = wm * 32 + mt * 16 + frow;
                aF[mt][0] = __float_as_uint(As_[(kb + fcol) * SMS + m]);
                aF[mt][1] = __float_as_uint(As_[(kb + fcol) * SMS + m + 8]);
                aF[mt][2] = __float_as_uint(As_[(kb + fcol + 4) * SMS + m]);
                aF[mt][3] = __float_as_uint(As_[(kb + fcol + 4) * SMS + m + 8]);
            }
            #pragma unroll
            for (int nt = 0; nt < 8; nt++) {
                const int n = wn * 64 + nt * 8 + frow;
                bF[nt][0] = __float_as_uint(Bs_[(kb + fcol) * SMS + n]);
                bF[nt][1] = __float_as_uint(Bs_[(kb + fcol + 4) * SMS + n]);
            }
            #pragma unroll
            for (int mt = 0; mt < 2; mt++)
                #pragma unroll
                for (int nt = 0; nt < 8; nt++)
                    mma_tf32(acc[mt][nt], aF[mt], bF[nt]);
        }

        if (more) {
            float* Ad = smem + (buf ^ 1) * ABUF;
            float* Bd = smem + BBASE + (buf ^ 1) * ABUF;
            float va[8] = {na0.x, na0.y, na0.z, na0.w, na1.x, na1.y, na1.z, na1.w};
            #pragma unroll
            for (int j = 0; j < 8; j++) Ad[(cA + j) * SMS + rA] = tf32f(va[j]);
            float4 v0 = make_float4(tf32f(nb0.x), tf32f(nb0.y), tf32f(nb0.z), tf32f(nb0.w));
            float4 v1 = make_float4(tf32f(nb1.x), tf32f(nb1.y), tf32f(nb1.z), tf32f(nb1.w));
            *(float4*)&Bd[rB * SMS + cB]     = v0;
            *(float4*)&Bd[rB * SMS + cB + 4] = v1;
        }
        __syncthreads();
        buf ^= 1;
    }

    if (MODE == MODE_QKV) {
        float* dst = (region == 0) ? C0 : (region == 1 ? C1 : C2);
        const float scale = (region == 0) ? 0.125f : 1.0f;
        #pragma unroll
        for (int mt = 0; mt < 2; mt++)
            #pragma unroll
            for (int nt = 0; nt < 8; nt++) {
                const int n = ncol0 + wn * 64 + nt * 8 + 2 * fcol;
                const int h = n >> 6, d = n & 63;
                const float bv0 = bsel[n], bv1 = bsel[n + 1];
                #pragma unroll
                for (int half = 0; half < 2; half++) {
                    const int m = by * BM + wm * 32 + mt * 16 + frow + half * 8;
                    const int b = m >> 10, l = m & 1023;
                    float2 o;
                    o.x = (acc[mt][nt][half * 2 + 0] + bv0) * scale;
                    o.y = (acc[mt][nt][half * 2 + 1] + bv1) * scale;
                    *(float2*)&dst[((((size_t)b * NHEAD + h) << 10) + l) * DK + d] = o;
                }
            }
    } else if (MODE == MODE_PART) {
        #pragma unroll
        for (int mt = 0; mt < 2; mt++)
            #pragma unroll
            for (int nt = 0; nt < 8; nt++) {
                const int n = ncol0 + wn * 64 + nt * 8 + 2 * fcol;
                #pragma unroll
                for (int half = 0; half < 2; half++) {
                    const int m = by * BM + wm * 32 + mt * 16 + frow + half * 8;
                    float2 o;
                    o.x = acc[mt][nt][half * 2 + 0];
                    o.y = acc[mt][nt][half * 2 + 1];
                    *(float2*)&C0[outoff + (size_t)m * N + n] = o;
                }
            }
    } else {
        #pragma unroll
        for (int mt = 0; mt < 2; mt++)
            #pragma unroll
            for (int nt = 0; nt < 8; nt++) {
                const int n = ncol0 + wn * 64 + nt * 8 + 2 * fcol;
                const float bv0 = bias0[n], bv1 = bias0[n + 1];
                #pragma unroll
                for (int half = 0; half < 2; half++) {
                    const int m = by * BM + wm * 32 + mt * 16 + frow + half * 8;
                    float vx = acc[mt][nt][half * 2 + 0] + bv0;
                    float vy = acc[mt][nt][half * 2 + 1] + bv1;
                    if (MODE == MODE_BIAS_RES) {
                        const float* rp = R + (size_t)m * N + n;
                        vx += rp[0]; vy += rp[1];
                    } else {
                        vx = fmaxf(vx, 0.0f); vy = fmaxf(vy, 0.0f);
                    }
                    float2 o; o.x = vx; o.y = vy;
                    *(float2*)&C0[(size_t)m * N + n] = o;
                }
            }
    }
}

// ---------------- split-K reduce ----------------
template<int SPLITK>
__global__ __launch_bounds__(256)
void reduce_kernel(const float* __restrict__ P, const float* __restrict__ bias,
                   const float* __restrict__ R, float* __restrict__ C, int MN, int N)
{
    const int i = (blockIdx.x * 256 + threadIdx.x) * 4;
    float4 s = *(const float4*)(P + i);
    #pragma unroll
    for (int z = 1; z < SPLITK; z++) {
        float4 p = *(const float4*)(P + (size_t)z * MN + i);
        s.x += p.x; s.y += p.y; s.z += p.z; s.w += p.w;
    }
    float4 bv = *(const float4*)(bias + (i % N));
    float4 rv = *(const float4*)(R + i);
    s.x += bv.x + rv.x;
    s.y += bv.y + rv.y;
    s.z += bv.z + rv.z;
    s.w += bv.w + rv.w;
    *(float4*)(C + i) = s;
}

// ---------------- relative-position bias MLP ----------------
__global__ __launch_bounds__(128)
void bias_kernel(const float* __restrict__ sx, const float* __restrict__ sy,
                 const float* __restrict__ P1, const float* __restrict__ pb1,
                 const float* __restrict__ P2, const float* __restrict__ pb2,
                 float* __restrict__ gbias)
{
    __shared__ float sP1[64], spb1[32], sP2[384], spb2[12];
    const int tid = threadIdx.x;
    if (tid < 64) sP1[tid] = P1[tid];
    if (tid < 32) spb1[tid] = pb1[tid];
    if (tid < 12) spb2[tid] = pb2[tid];
    for (int i = tid; i < 384; i += 128) sP2[i] = P2[i];
    __syncthreads();

    const int k = blockIdx.x * 128 + tid;
    const int q = blockIdx.y;
    const int b = blockIdx.z;

    const float xq = sx[b * NL + q], yq = sy[b * NL + q];
    float rx = fminf(fmaxf(xq - sx[b * NL + k], -1000.0f), 1000.0f) * 0.001f;
    float ry = fminf(fmaxf(yq - sy[b * NL + k], -1000.0f), 1000.0f) * 0.001f;

    float hbuf[32];
    #pragma unroll
    for (int j = 0; j < 32; j++) {
        float v = fmaf(rx, sP1[j], fmaf(ry, sP1[32 + j], spb1[j]));
        hbuf[j] = fmaxf(v, 0.0f);
    }
    #pragma unroll
    for (int h = 0; h < NHEAD; h++) {
        float s = spb2[h];
        #pragma unroll
        for (int j = 0; j < 32; j++) s = fmaf(hbuf[j], sP2[j * NHEAD + h], s);
        gbias[((((size_t)b * NHEAD + h) << 10) + q) * NL + k] = s;
    }
}

// ---------------- flash attention: tf32 mma, 64x64 tiles ----------------
// Qs [d][q] s=72, Ks [d][c] s=72, Vs [k][d] s=72, Ss [q][c] s=68
#define AQ_S 72
#define AS_S 68
#define AT_KS (64*AQ_S)
#define AT_VS (2*64*AQ_S)
#define AT_SS (3*64*AQ_S)
#define ATTN_SMEM ((3*64*AQ_S + 64*AS_S)*4)

__global__ __launch_bounds__(256)
void attn_kernel(const float* __restrict__ Qg, const float* __restrict__ Kg,
                 const float* __restrict__ Vg, const float* __restrict__ biasg,
                 float* __restrict__ Og)
{
    extern __shared__ float smem[];
    float* Qs = smem;
    float* Ks = smem + AT_KS;
    float* Vs = smem + AT_VS;
    float* Ss = smem + AT_SS;
    __shared__ float m_s[64], l_s[64], cf_s[64];

    const int b = blockIdx.z, h = blockIdx.y, q0 = blockIdx.x * 64;
    const int bh = b * NHEAD + h;
    const int tid = threadIdx.x;
    const int lane = tid & 31, warp = tid >> 5;
    const int wm = warp >> 1, wn = warp & 1;     // 4(m) x 2(n)
    const int frow = lane >> 2, fcol = lane & 3;

    // load Q transposed [d][q], tf32-rounded (Q already pre-scaled by 0.125)
    {
        const int r = tid >> 2;
        const int d4 = (tid & 3) * 16;
        const float* qp = Qg + (((size_t)bh << 10) + q0 + r) * DK + d4;
        #pragma unroll
        for (int t = 0; t < 4; t++) {
            float4 v = *(const float4*)(qp + t * 4);
            const int d = d4 + t * 4;
            Qs[(d + 0) * AQ_S + r] = tf32f(v.x);
            Qs[(d + 1) * AQ_S + r] = tf32f(v.y);
            Qs[(d + 2) * AQ_S + r] = tf32f(v.z);
            Qs[(d + 3) * AQ_S + r] = tf32f(v.w);
        }
    }
    if (tid < 64) { m_s[tid] = -1e30f; l_s[tid] = 0.0f; }

    float oacc[4][4];
    #pragma unroll
    for (int i = 0; i < 4; i++)
        #pragma unroll
        for (int j = 0; j < 4; j++) oacc[i][j] = 0.0f;

    __syncthreads();

    for (int kt = 0; kt < 16; kt++) {
        const int k0 = kt * 64;
        // load K transposed [d][c] + V [k][d], tf32-rounded
        {
            const int r = tid >> 2;
            const int d4 = (tid & 3) * 16;
            const float* kp = Kg + (((size_t)bh << 10) + k0 + r) * DK + d4;
            const float* vp = Vg + (((size_t)bh << 10) + k0 + r) * DK + d4;
            #pragma unroll
            for (int t = 0; t < 4; t++) {
                float4 kv = *(const float4*)(kp + t * 4);
                const int d = d4 + t * 4;
                Ks[(d + 0) * AQ_S + r] = tf32f(kv.x);
                Ks[(d + 1) * AQ_S + r] = tf32f(kv.y);
                Ks[(d + 2) * AQ_S + r] = tf32f(kv.z);
                Ks[(d + 3) * AQ_S + r] = tf32f(kv.w);
                float4 vv = *(const float4*)(vp + t * 4);
                float4 vc = make_float4(tf32f(vv.x), tf32f(vv.y), tf32f(vv.z), tf32f(vv.w));
                *(float4*)&Vs[r * AQ_S + d] = vc;
            }
        }
        __syncthreads();

        // stage 1: S = Q K^T (tensor), contraction over d=64
        float sacc[4][4];
        #pragma unroll
        for (int i = 0; i < 4; i++)
            #pragma unroll
            for (int j = 0; j < 4; j++) sacc[i][j] = 0.0f;

        const int m = wm * 16 + frow;
        #pragma unroll
        for (int ks = 0; ks < 8; ks++) {
            const int kb = ks * 8;
            uint32_t aF[4];
            aF[0] = __float_as_uint(Qs[(kb + fcol) * AQ_S + m]);
            aF[1] = __float_as_uint(Qs[(kb + fcol) * AQ_S + m + 8]);
            aF[2] = __float_as_uint(Qs[(kb + fcol + 4) * AQ_S + m]);
            aF[3] = __float_as_uint(Qs[(kb + fcol + 4) * AQ_S + m + 8]);
            #pragma unroll
            for (int nt = 0; nt < 4; nt++) {
                const int n = wn * 32 + nt * 8 + frow;
                uint32_t bF[2];
                bF[0] = __float_as_uint(Ks[(kb + fcol) * AQ_S + n]);
                bF[1] = __float_as_uint(Ks[(kb + fcol + 4) * AQ_S + n]);
                mma_tf32(sacc[nt], aF, bF);
            }
        }

        // add bias from gmem, store S tile to smem
        #pragma unroll
        for (int nt = 0; nt < 4; nt++) {
            const int c = wn * 32 + nt * 8 + 2 * fcol;
            const int qr = wm * 16 + frow;
            const float* bp0 = biasg + ((((size_t)bh << 10) + q0 + qr) << 10) + k0 + c;
            float2 bv0 = *(const float2*)bp0;
            Ss[qr * AS_S + c]     = sacc[nt][0] + bv0.x;
            Ss[qr * AS_S + c + 1] = sacc[nt][1] + bv0.y;
            const float* bp1 = biasg + ((((size_t)bh << 10) + q0 + qr + 8) << 10) + k0 + c;
            float2 bv1 = *(const float2*)bp1;
            Ss[(qr + 8) * AS_S + c]     = sacc[nt][2] + bv1.x;
            Ss[(qr + 8) * AS_S + c + 1] = sacc[nt][3] + bv1.y;
        }
        __syncthreads();

        // stage 2: online softmax, 4 threads/row; P written tf32-rounded
        {
            const int r = tid >> 2;
            float* srow = &Ss[r * AS_S + (tid & 3) * 16];
            const float mold = m_s[r];
            float mx = -1e30f;
            #pragma unroll
            for (int c = 0; c < 16; c++) mx = fmaxf(mx, srow[c]);
            mx = fmaxf(mx, __shfl_xor_sync(0xffffffffu, mx, 1));
            mx = fmaxf(mx, __shfl_xor_sync(0xffffffffu, mx, 2));
            mx = fmaxf(mx, mold);
            float sum = 0.0f;
            #pragma unroll
            for (int c = 0; c < 16; c++) {
                float p = tf32f(__expf(srow[c] - mx));
                srow[c] = p;
                sum += p;
            }
            sum += __shfl_xor_sync(0xffffffffu, sum, 1);
            sum += __shfl_xor_sync(0xffffffffu, sum, 2);
            if ((tid & 3) == 0) {
                float cf = __expf(mold - mx);
                l_s[r] = l_s[r] * cf + sum;
                m_s[r] = mx;
                cf_s[r] = cf;
            }
        }
        __syncthreads();

        // stage 3: rescale + O += P @ V (tensor), contraction over kpos=64
        {
            const int qr = wm * 16 + frow;
            const float cf0 = cf_s[qr], cf1 = cf_s[qr + 8];
            #pragma unroll
            for (int nt = 0; nt < 4; nt++) {
                oacc[nt][0] *= cf0; oacc[nt][1] *= cf0;
                oacc[nt][2] *= cf1; oacc[nt][3] *= cf1;
            }
        }
        #pragma unroll
        for (int ks = 0; ks < 8; ks++) {
            const int kb = ks * 8;
            uint32_t aF[4];
            aF[0] = __float_as_uint(Ss[m * AS_S + kb + fcol]);
            aF[1] = __float_as_uint(Ss[(m + 8) * AS_S + kb + fcol]);
            aF[2] = __float_as_uint(Ss[m * AS_S + kb + fcol + 4]);
            aF[3] = __float_as_uint(Ss[(m + 8) * AS_S + kb + fcol + 4]);
            #pragma unroll
            for (int nt = 0; nt < 4; nt++) {
                const int n = wn * 32 + nt * 8 + frow;
                uint32_t bF[2];
                bF[0] = __float_as_uint(Vs[(kb + fcol) * AQ_S + n]);
                bF[1] = __float_as_uint(Vs[(kb + fcol + 4) * AQ_S + n]);
                mma_tf32(oacc[nt], aF, bF);
            }
        }
        __syncthreads();
    }

    // epilogue: O[b, q, h*64 + d] = oacc / l
    {
        const int qr = wm * 16 + frow;
        const float inv0 = 1.0f / l_s[qr], inv1 = 1.0f / l_s[qr + 8];
        #pragma unroll
        for (int nt = 0; nt < 4; nt++) {
            const int d = wn * 32 + nt * 8 + 2 * fcol;
            float2 o0; o0.x = oacc[nt][0] * inv0; o0.y = oacc[nt][1] * inv0;
            *(float2*)&Og[((size_t)b * NL + q0 + qr) * D_MODEL + h * DK + d] = o0;
            float2 o1; o1.x = oacc[nt][2] * inv1; o1.y = oacc[nt][3] * inv1;
            *(float2*)&Og[((size_t)b * NL + q0 + qr + 8) * D_MODEL + h * DK + d] = o1;
        }
    }
}

// ---------------- LayerNorm ----------------
__global__ __launch_bounds__(256)
void ln_kernel(const float* __restrict__ X, const float* __restrict__ gam,
               const float* __restrict__ bet, float* __restrict__ Y)
{
    const int row = blockIdx.x;
    const float* x = X + (size_t)row * D_MODEL;
    float* y = Y + (size_t)row * D_MODEL;

    float s = 0.0f, sq = 0.0f;
    for (int i = threadIdx.x; i < D_MODEL; i += 256) {
        float v = x[i];
        s += v;
        sq += v * v;
    }
    #pragma unroll
    for (int o = 16; o; o >>= 1) {
        s  += __shfl_down_sync(0xffffffffu, s, o);
        sq += __shfl_down_sync(0xffffffffu, sq, o);
    }
    __shared__ float sm0[8], sm1[8];
    const int wid = threadIdx.x >> 5, lane = threadIdx.x & 31;
    if (lane == 0) { sm0[wid] = s; sm1[wid] = sq; }
    __syncthreads();
    if (threadIdx.x == 0) {
        float a = 0.0f, c = 0.0f;
        #pragma unroll
        for (int w = 0; w < 8; w++) { a += sm0[w]; c += sm1[w]; }
        sm0[0] = a; sm1[0] = c;
    }
    __syncthreads();
    const float mean = sm0[0] * (1.0f / D_MODEL);
    const float var  = sm1[0] * (1.0f / D_MODEL) - mean * mean;
    const float inv = rsqrtf(var + 1e-5f);
    for (int i = threadIdx.x; i < D_MODEL; i += 256)
        y[i] = (x[i] - mean) * inv * gam[i] + bet[i];
}

// ---------------- launch ----------------
extern "C" void kernel_launch(void* const* d_in, const int* in_sizes, int n_in,
                              void* d_out, int out_size)
{
    const float* src = (const float*)d_in[0];
    const float* sx  = (const float*)d_in[1];
    const float* sy  = (const float*)d_in[2];
    const float* Wq  = (const float*)d_in[3];
    const float* bq  = (const float*)d_in[4];
    const float* Wk  = (const float*)d_in[5];
    const float* bk  = (const float*)d_in[6];
    const float* Wv  = (const float*)d_in[7];
    const float* bv  = (const float*)d_in[8];
    const float* Wo  = (const float*)d_in[9];
    const float* bo  = (const float*)d_in[10];
    const float* P1  = (const float*)d_in[11];
    const float* pb1 = (const float*)d_in[12];
    const float* P2  = (const float*)d_in[13];
    const float* pb2 = (const float*)d_in[14];
    const float* W1  = (const float*)d_in[15];
    const float* b1  = (const float*)d_in[16];
    const float* W2  = (const float*)d_in[17];
    const float* b2  = (const float*)d_in[18];
    const float* g1  = (const float*)d_in[19];
    const float* be1 = (const float*)d_in[20];
    const float* g2  = (const float*)d_in[21];
    const float* be2 = (const float*)d_in[22];

    float* scratch = nullptr;
    cudaGetSymbolAddress((void**)&scratch, g_scratch);
    float* Q    = scratch + OFF_Q;
    float* K    = scratch + OFF_K;
    float* V    = scratch + OFF_V;
    float* Bias = scratch + OFF_BIAS;
    float* AO   = scratch + OFF_AO;
    float* X1   = scratch + OFF_X1;
    float* X    = scratch + OFF_X;
    float* Hb   = scratch + OFF_H;
    float* X2   = scratch + OFF_X2;
    float* PART = scratch + OFF_PART;

    cudaFuncSetAttribute(attn_kernel, cudaFuncAttributeMaxDynamicSharedMemorySize, ATTN_SMEM);

    const int MN = MTOT * D_MODEL;

    // 1. fused QKV projection (tf32 tensor) -> (b,h,l,dk), Q pre-scaled
    tgemm_kernel<MODE_QKV><<<dim3(2304 / BN, MTOT / BM), 256>>>(
        src, Wq, Wk, Wv, bq, bk, bv, nullptr, Q, K, V, MTOT, 2304, D_MODEL, D_MODEL);

    // 2. relative-position bias
    bias_kernel<<<dim3(NL / 128, NL, NB), 128>>>(sx, sy, P1, pb1, P2, pb2, Bias);

    // 3. flash attention (tf32 tensor)
    attn_kernel<<<dim3(NL / 64, NHEAD, NB), 256, ATTN_SMEM>>>(Q, K, V, Bias, AO);

    // 4. output projection split-K=4 + reduce(bias, residual)
    tgemm_kernel<MODE_PART><<<dim3(D_MODEL / BN, MTOT / BM, 4), 256>>>(
        AO, Wo, nullptr, nullptr, nullptr, nullptr, nullptr, nullptr,
        PART, nullptr, nullptr, MTOT, D_MODEL, 192, D_MODEL);
    reduce_kernel<4><<<MN / 1024, 256>>>(PART, bo, src, X1, MN, D_MODEL);

    // 5. LayerNorm 1
    ln_kernel<<<MTOT, 256>>>(X1, g1, be1, X);

    // 6. FFN up + ReLU
    tgemm_kernel<MODE_BIAS_RELU><<<dim3(FF / BN, MTOT / BM), 256>>>(
        X, W1, nullptr, nullptr, b1, nullptr, nullptr, nullptr, Hb, nullptr, nullptr,
        MTOT, FF, D_MODEL, D_MODEL);

    // 7. FFN down split-K=8 + reduce(bias, residual)
    tgemm_kernel<MODE_PART><<<dim3(D_MODEL / BN, MTOT / BM, 8), 256>>>(
        Hb, W2, nullptr, nullptr, nullptr, nullptr, nullptr, nullptr,
        PART, nullptr, nullptr, MTOT, D_MODEL, 384, FF);
    reduce_kernel<8><<<MN / 1024, 256>>>(PART, b2, X, X2, MN, D_MODEL);

    // 8. LayerNorm 2 -> output
    ln_kernel<<<MTOT, 256>>>(X2, g2, be2, (float*)d_out);
}

// round 10
// speedup vs baseline: 1.1201x; 1.1201x over previous
#include <cuda_runtime.h>
#include <math.h>
#include <stddef.h>
#include <stdint.h>

#define D_MODEL 768
#define NHEAD 12
#define DK 64
#define FF 3072
#define NB 2
#define NL 1024
#define MTOT (NB*NL)   // 2048

// ---------------- scratch ----------------
#define OFF_Q    0
#define OFF_K    1572864
#define OFF_V    3145728
#define OFF_BIAS 4718592
#define OFF_AO   29884416
#define OFF_X    33030144
#define OFF_H    34603008
#define OFF_PART 42467328
#define SCRATCH_TOTAL (42467328 + 8*1572864)

__device__ float g_scratch[SCRATCH_TOTAL];

#define BM 128
#define BN 128

#define MODE_QKV 0
#define MODE_BIAS_RES 1
#define MODE_BIAS_RELU 2
#define MODE_PART 3

__device__ __forceinline__ uint32_t f2tf32(float x) {
    uint32_t r;
    asm("cvt.rna.tf32.f32 %0, %1;" : "=r"(r) : "f"(x));
    return r;
}
__device__ __forceinline__ float tf32f(float x) {
    return __uint_as_float(f2tf32(x));
}
__device__ __forceinline__ void mma_tf32(float* c, const uint32_t* a, const uint32_t* b) {
    asm volatile("mma.sync.aligned.m16n8k8.row.col.f32.tf32.tf32.f32 "
        "{%0,%1,%2,%3}, {%4,%5,%6,%7}, {%8,%9}, {%0,%1,%2,%3};"
        : "+f"(c[0]), "+f"(c[1]), "+f"(c[2]), "+f"(c[3])
        : "r"(a[0]), "r"(a[1]), "r"(a[2]), "r"(a[3]), "r"(b[0]), "r"(b[1]));
}
__device__ __forceinline__ void cp16(uint32_t dst, const float* src) {
    asm volatile("cp.async.cg.shared.global [%0], [%1], 16;" :: "r"(dst), "l"(src));
}
#define CP_COMMIT() asm volatile("cp.async.commit_group;")
template<int N> __device__ __forceinline__ void cp_wait() {
    asm volatile("cp.async.wait_group %0;" :: "n"(N));
}

// ---------------- tensor-core GEMM: 128x128x16 tiles, cp.async 3-stage ----------------
// per stage: A[m][k] 128x16 stride 20 (2560 f), B[k][n] 16x128 stride 136 (2176 f)
#define ASTR 20
#define BSTR 136
#define SSTRIDE 4736            // floats per stage
#define TG_SMEM (3 * SSTRIDE * 4)

template<int MODE>
__global__ __launch_bounds__(256, 2)
void tgemm_kernel(const float* __restrict__ A,
                  const float* __restrict__ B0, const float* __restrict__ B1, const float* __restrict__ B2,
                  const float* __restrict__ bias0, const float* __restrict__ bias1, const float* __restrict__ bias2,
                  const float* __restrict__ R,
                  float* __restrict__ C0, float* __restrict__ C1, float* __restrict__ C2,
                  int M, int N, int K, int lda)
{
    extern __shared__ float smem[];
    const uint32_t smem_u32 = (uint32_t)__cvta_generic_to_shared(smem);

    const int bx = blockIdx.x, by = blockIdx.y;
    const int tid = threadIdx.x;

    const float* Asrc = A;
    const float* Bsel = B0;
    const float* bsel = bias0;
    size_t outoff = 0;
    int ncol0 = bx * BN;
    int Nw = N;
    int region = 0;
    if (MODE == MODE_QKV) {
        region = ncol0 / 768;
        Bsel = (region == 0) ? B0 : (region == 1 ? B1 : B2);
        bsel = (region == 0) ? bias0 : (region == 1 ? bias1 : bias2);
        ncol0 -= region * 768;
        Nw = 768;
    }
    if (MODE == MODE_PART) {
        const int z = blockIdx.z;
        Asrc = A + (size_t)z * K;
        Bsel = B0 + (size_t)z * K * N;
        outoff = (size_t)z * ((size_t)M * N);
    }

    // loader indices
    const int lmA = tid >> 1, lk8 = (tid & 1) * 8;      // A: row, k-offset (2 chunks)
    const int lkB = tid >> 5, ln4 = (tid & 31) * 4;     // B: k-row, n-offset (2 chunks, +8 rows)
    const float* ApBase = Asrc + (size_t)(by * BM + lmA) * lda + lk8;
    const float* BpBase = Bsel + (size_t)lkB * Nw + ncol0 + ln4;

    const int NK = K / 16;

    // fragment mapping
    const int lane = tid & 31, warp = tid >> 5;
    const int wm = warp >> 1, wn = warp & 1;
    const int frow = lane >> 2, fcol = lane & 3;

    float acc[2][8][4];
    #pragma unroll
    for (int i = 0; i < 2; i++)
        #pragma unroll
        for (int j = 0; j < 8; j++)
            #pragma unroll
            for (int r = 0; r < 4; r++) acc[i][j][r] = 0.0f;

    // stage loader
    auto load_stage = [&](int kt, int s) {
        if (kt < NK) {
            const int k0 = kt * 16;
            const uint32_t sa = smem_u32 + (uint32_t)(s * SSTRIDE) * 4;
            const uint32_t sb = sa + 2560 * 4;
            const float* srcA = ApBase + k0;
            cp16(sa + (uint32_t)(lmA * ASTR + lk8) * 4, srcA);
            cp16(sa + (uint32_t)(lmA * ASTR + lk8 + 4) * 4, srcA + 4);
            const float* srcB = BpBase + (size_t)k0 * Nw;
            cp16(sb + (uint32_t)(lkB * BSTR + ln4) * 4, srcB);
            cp16(sb + (uint32_t)((lkB + 8) * BSTR + ln4) * 4, srcB + (size_t)8 * Nw);
        }
        CP_COMMIT();
    };

    load_stage(0, 0);
    load_stage(1, 1);

    int buf = 0;
    for (int kt = 0; kt < NK; kt++) {
        cp_wait<1>();
        __syncthreads();

        int nbuf = buf + 2; if (nbuf >= 3) nbuf -= 3;
        load_stage(kt + 2, nbuf);

        const float* As_ = smem + buf * SSTRIDE;
        const float* Bs_ = smem + buf * SSTRIDE + 2560;

        #pragma unroll
        for (int ks = 0; ks < 2; ks++) {
            const int kb = ks * 8;
            uint32_t aF[2][4], bF[8][2];
            #pragma unroll
            for (int mt = 0; mt < 2; mt++) {
                const int m = wm * 32 + mt * 16 + frow;
                aF[mt][0] = __float_as_uint(As_[m * ASTR + kb + fcol]);
                aF[mt][1] = __float_as_uint(As_[(m + 8) * ASTR + kb + fcol]);
                aF[mt][2] = __float_as_uint(As_[m * ASTR + kb + fcol + 4]);
                aF[mt][3] = __float_as_uint(As_[(m + 8) * ASTR + kb + fcol + 4]);
            }
            #pragma unroll
            for (int nt = 0; nt < 8; nt++) {
                const int n = wn * 64 + nt * 8 + frow;
                bF[nt][0] = __float_as_uint(Bs_[(kb + fcol) * BSTR + n]);
                bF[nt][1] = __float_as_uint(Bs_[(kb + fcol + 4) * BSTR + n]);
            }
            #pragma unroll
            for (int mt = 0; mt < 2; mt++)
                #pragma unroll
                for (int nt = 0; nt < 8; nt++)
                    mma_tf32(acc[mt][nt], aF[mt], bF[nt]);
        }

        buf = buf + 1; if (buf >= 3) buf -= 3;
    }

    // ---------------- epilogue ----------------
    if (MODE == MODE_QKV) {
        float* dst = (region == 0) ? C0 : (region == 1 ? C1 : C2);
        const float scale = (region == 0) ? 0.125f : 1.0f;
        #pragma unroll
        for (int mt = 0; mt < 2; mt++)
            #pragma unroll
            for (int nt = 0; nt < 8; nt++) {
                const int n = ncol0 + wn * 64 + nt * 8 + 2 * fcol;
                const int h = n >> 6, d = n & 63;
                const float bv0 = bsel[n], bv1 = bsel[n + 1];
                #pragma unroll
                for (int half = 0; half < 2; half++) {
                    const int m = by * BM + wm * 32 + mt * 16 + frow + half * 8;
                    const int b = m >> 10, l = m & 1023;
                    float2 o;
                    o.x = (acc[mt][nt][half * 2 + 0] + bv0) * scale;
                    o.y = (acc[mt][nt][half * 2 + 1] + bv1) * scale;
                    *(float2*)&dst[((((size_t)b * NHEAD + h) << 10) + l) * DK + d] = o;
                }
            }
    } else if (MODE == MODE_PART) {
        #pragma unroll
        for (int mt = 0; mt < 2; mt++)
            #pragma unroll
            for (int nt = 0; nt < 8; nt++) {
                const int n = ncol0 + wn * 64 + nt * 8 + 2 * fcol;
                #pragma unroll
                for (int half = 0; half < 2; half++) {
                    const int m = by * BM + wm * 32 + mt * 16 + frow + half * 8;
                    float2 o;
                    o.x = acc[mt][nt][half * 2 + 0];
                    o.y = acc[mt][nt][half * 2 + 1];
                    *(float2*)&C0[outoff + (size_t)m * N + n] = o;
                }
            }
    } else {
        #pragma unroll
        for (int mt = 0; mt < 2; mt++)
            #pragma unroll
            for (int nt = 0; nt < 8; nt++) {
                const int n = ncol0 + wn * 64 + nt * 8 + 2 * fcol;
                const float bv0 = bias0[n], bv1 = bias0[n + 1];
                #pragma unroll
                for (int half = 0; half < 2; half++) {
                    const int m = by * BM + wm * 32 + mt * 16 + frow + half * 8;
                    float vx = acc[mt][nt][half * 2 + 0] + bv0;
                    float vy = acc[mt][nt][half * 2 + 1] + bv1;
                    if (MODE == MODE_BIAS_RES) {
                        const float* rp = R + (size_t)m * N + n;
                        vx += rp[0]; vy += rp[1];
                    } else {
                        vx = fmaxf(vx, 0.0f); vy = fmaxf(vy, 0.0f);
                    }
                    float2 o; o.x = vx; o.y = vy;
                    *(float2*)&C0[(size_t)m * N + n] = o;
                }
            }
    }
}

// ---------------- fused split-K reduce + bias + residual + LayerNorm ----------------
template<int SPLITK>
__global__ __launch_bounds__(192)
void reduce_ln_kernel(const float* __restrict__ P, const float* __restrict__ bias,
                      const float* __restrict__ R, const float* __restrict__ gam,
                      const float* __restrict__ bet, float* __restrict__ Y, int MN)
{
    const int row = blockIdx.x;
    const int t = threadIdx.x;          // 192 threads, 4 cols each
    const int col = t * 4;
    const size_t i = (size_t)row * D_MODEL + col;

    float4 s = *(const float4*)(P + i);
    #pragma unroll
    for (int z = 1; z < SPLITK; z++) {
        float4 p = *(const float4*)(P + (size_t)z * MN + i);
        s.x += p.x; s.y += p.y; s.z += p.z; s.w += p.w;
    }
    float4 bv = *(const float4*)(bias + col);
    float4 rv = *(const float4*)(R + i);
    s.x += bv.x + rv.x;
    s.y += bv.y + rv.y;
    s.z += bv.z + rv.z;
    s.w += bv.w + rv.w;

    float a  = s.x + s.y + s.z + s.w;
    float q  = s.x * s.x + s.y * s.y + s.z * s.z + s.w * s.w;
    #pragma unroll
    for (int o = 16; o; o >>= 1) {
        a += __shfl_down_sync(0xffffffffu, a, o);
        q += __shfl_down_sync(0xffffffffu, q, o);
    }
    __shared__ float sm0[6], sm1[6], bcast[2];
    const int wid = t >> 5, lanei = t & 31;
    if (lanei == 0) { sm0[wid] = a; sm1[wid] = q; }
    __syncthreads();
    if (t == 0) {
        float ta = 0.0f, tq = 0.0f;
        #pragma unroll
        for (int w = 0; w < 6; w++) { ta += sm0[w]; tq += sm1[w]; }
        const float mean = ta * (1.0f / D_MODEL);
        const float var  = tq * (1.0f / D_MODEL) - mean * mean;
        bcast[0] = mean;
        bcast[1] = rsqrtf(var + 1e-5f);
    }
    __syncthreads();
    const float mean = bcast[0], inv = bcast[1];

    float4 gv = *(const float4*)(gam + col);
    float4 ev = *(const float4*)(bet + col);
    float4 y;
    y.x = (s.x - mean) * inv * gv.x + ev.x;
    y.y = (s.y - mean) * inv * gv.y + ev.y;
    y.z = (s.z - mean) * inv * gv.z + ev.z;
    y.w = (s.w - mean) * inv * gv.w + ev.w;
    *(float4*)(Y + i) = y;
}

// ---------------- relative-position bias MLP ----------------
__global__ __launch_bounds__(128)
void bias_kernel(const float* __restrict__ sx, const float* __restrict__ sy,
                 const float* __restrict__ P1, const float* __restrict__ pb1,
                 const float* __restrict__ P2, const float* __restrict__ pb2,
                 float* __restrict__ gbias)
{
    __shared__ float sP1[64], spb1[32], sP2[384], spb2[12];
    const int tid = threadIdx.x;
    if (tid < 64) sP1[tid] = P1[tid];
    if (tid < 32) spb1[tid] = pb1[tid];
    if (tid < 12) spb2[tid] = pb2[tid];
    for (int i = tid; i < 384; i += 128) sP2[i] = P2[i];
    __syncthreads();

    const int k = blockIdx.x * 128 + tid;
    const int q = blockIdx.y;
    const int b = blockIdx.z;

    const float xq = sx[b * NL + q], yq = sy[b * NL + q];
    float rx = fminf(fmaxf(xq - sx[b * NL + k], -1000.0f), 1000.0f) * 0.001f;
    float ry = fminf(fmaxf(yq - sy[b * NL + k], -1000.0f), 1000.0f) * 0.001f;

    float hbuf[32];
    #pragma unroll
    for (int j = 0; j < 32; j++) {
        float v = fmaf(rx, sP1[j], fmaf(ry, sP1[32 + j], spb1[j]));
        hbuf[j] = fmaxf(v, 0.0f);
    }
    #pragma unroll
    for (int h = 0; h < NHEAD; h++) {
        float s = spb2[h];
        #pragma unroll
        for (int j = 0; j < 32; j++) s = fmaf(hbuf[j], sP2[j * NHEAD + h], s);
        gbias[((((size_t)b * NHEAD + h) << 10) + q) * NL + k] = s;
    }
}

// ---------------- flash attention: tf32 mma, 64x64 tiles ----------------
#define AQ_S 72
#define AS_S 68
#define AT_KS (64*AQ_S)
#define AT_VS (2*64*AQ_S)
#define AT_SS (3*64*AQ_S)
#define ATTN_SMEM ((3*64*AQ_S + 64*AS_S)*4)

__global__ __launch_bounds__(256)
void attn_kernel(const float* __restrict__ Qg, const float* __restrict__ Kg,
                 const float* __restrict__ Vg, const float* __restrict__ biasg,
                 float* __restrict__ Og)
{
    extern __shared__ float smem[];
    float* Qs = smem;
    float* Ks = smem + AT_KS;
    float* Vs = smem + AT_VS;
    float* Ss = smem + AT_SS;
    __shared__ float m_s[64], l_s[64], cf_s[64];

    const int b = blockIdx.z, h = blockIdx.y, q0 = blockIdx.x * 64;
    const int bh = b * NHEAD + h;
    const int tid = threadIdx.x;
    const int lane = tid & 31, warp = tid >> 5;
    const int wm = warp >> 1, wn = warp & 1;
    const int frow = lane >> 2, fcol = lane & 3;

    {
        const int r = tid >> 2;
        const int d4 = (tid & 3) * 16;
        const float* qp = Qg + (((size_t)bh << 10) + q0 + r) * DK + d4;
        #pragma unroll
        for (int t = 0; t < 4; t++) {
            float4 v = *(const float4*)(qp + t * 4);
            const int d = d4 + t * 4;
            Qs[(d + 0) * AQ_S + r] = tf32f(v.x);
            Qs[(d + 1) * AQ_S + r] = tf32f(v.y);
            Qs[(d + 2) * AQ_S + r] = tf32f(v.z);
            Qs[(d + 3) * AQ_S + r] = tf32f(v.w);
        }
    }
    if (tid < 64) { m_s[tid] = -1e30f; l_s[tid] = 0.0f; }

    float oacc[4][4];
    #pragma unroll
    for (int i = 0; i < 4; i++)
        #pragma unroll
        for (int j = 0; j < 4; j++) oacc[i][j] = 0.0f;

    __syncthreads();

    for (int kt = 0; kt < 16; kt++) {
        const int k0 = kt * 64;
        {
            const int r = tid >> 2;
            const int d4 = (tid & 3) * 16;
            const float* kp = Kg + (((size_t)bh << 10) + k0 + r) * DK + d4;
            const float* vp = Vg + (((size_t)bh << 10) + k0 + r) * DK + d4;
            #pragma unroll
            for (int t = 0; t < 4; t++) {
                float4 kv = *(const float4*)(kp + t * 4);
                const int d = d4 + t * 4;
                Ks[(d + 0) * AQ_S + r] = tf32f(kv.x);
                Ks[(d + 1) * AQ_S + r] = tf32f(kv.y);
                Ks[(d + 2) * AQ_S + r] = tf32f(kv.z);
                Ks[(d + 3) * AQ_S + r] = tf32f(kv.w);
                float4 vv = *(const float4*)(vp + t * 4);
                float4 vc = make_float4(tf32f(vv.x), tf32f(vv.y), tf32f(vv.z), tf32f(vv.w));
                *(float4*)&Vs[r * AQ_S + d] = vc;
            }
        }
        __syncthreads();

        float sacc[4][4];
        #pragma unroll
        for (int i = 0; i < 4; i++)
            #pragma unroll
            for (int j = 0; j < 4; j++) sacc[i][j] = 0.0f;

        const int m = wm * 16 + frow;
        #pragma unroll
        for (int ks = 0; ks < 8; ks++) {
            const int kb = ks * 8;
            uint32_t aF[4];
            aF[0] = __float_as_uint(Qs[(kb + fcol) * AQ_S + m]);
            aF[1] = __float_as_uint(Qs[(kb + fcol) * AQ_S + m + 8]);
            aF[2] = __float_as_uint(Qs[(kb + fcol + 4) * AQ_S + m]);
            aF[3] = __float_as_uint(Qs[(kb + fcol + 4) * AQ_S + m + 8]);
            #pragma unroll
            for (int nt = 0; nt < 4; nt++) {
                const int n = wn * 32 + nt * 8 + frow;
                uint32_t bF[2];
                bF[0] = __float_as_uint(Ks[(kb + fcol) * AQ_S + n]);
                bF[1] = __float_as_uint(Ks[(kb + fcol + 4) * AQ_S + n]);
                mma_tf32(sacc[nt], aF, bF);
            }
        }

        #pragma unroll
        for (int nt = 0; nt < 4; nt++) {
            const int c = wn * 32 + nt * 8 + 2 * fcol;
            const int qr = wm * 16 + frow;
            const float* bp0 = biasg + ((((size_t)bh << 10) + q0 + qr) << 10) + k0 + c;
            float2 bv0 = *(const float2*)bp0;
            Ss[qr * AS_S + c]     = sacc[nt][0] + bv0.x;
            Ss[qr * AS_S + c + 1] = sacc[nt][1] + bv0.y;
            const float* bp1 = biasg + ((((size_t)bh << 10) + q0 + qr + 8) << 10) + k0 + c;
            float2 bv1 = *(const float2*)bp1;
            Ss[(qr + 8) * AS_S + c]     = sacc[nt][2] + bv1.x;
            Ss[(qr + 8) * AS_S + c + 1] = sacc[nt][3] + bv1.y;
        }
        __syncthreads();

        {
            const int r = tid >> 2;
            float* srow = &Ss[r * AS_S + (tid & 3) * 16];
            const float mold = m_s[r];
            float mx = -1e30f;
            #pragma unroll
            for (int c = 0; c < 16; c++) mx = fmaxf(mx, srow[c]);
            mx = fmaxf(mx, __shfl_xor_sync(0xffffffffu, mx, 1));
            mx = fmaxf(mx, __shfl_xor_sync(0xffffffffu, mx, 2));
            mx = fmaxf(mx, mold);
            float sum = 0.0f;
            #pragma unroll
            for (int c = 0; c < 16; c++) {
                float p = tf32f(__expf(srow[c] - mx));
                srow[c] = p;
                sum += p;
            }
            sum += __shfl_xor_sync(0xffffffffu, sum, 1);
            sum += __shfl_xor_sync(0xffffffffu, sum, 2);
            if ((tid & 3) == 0) {
                float cf = __expf(mold - mx);
                l_s[r] = l_s[r] * cf + sum;
                m_s[r] = mx;
                cf_s[r] = cf;
            }
        }
        __syncthreads();

        {
            const int qr = wm * 16 + frow;
            const float cf0 = cf_s[qr], cf1 = cf_s[qr + 8];
            #pragma unroll
            for (int nt = 0; nt < 4; nt++) {
                oacc[nt][0] *= cf0; oacc[nt][1] *= cf0;
                oacc[nt][2] *= cf1; oacc[nt][3] *= cf1;
            }
        }
        #pragma unroll
        for (int ks = 0; ks < 8; ks++) {
            const int kb = ks * 8;
            uint32_t aF[4];
            aF[0] = __float_as_uint(Ss[m * AS_S + kb + fcol]);
            aF[1] = __float_as_uint(Ss[(m + 8) * AS_S + kb + fcol]);
            aF[2] = __float_as_uint(Ss[m * AS_S + kb + fcol + 4]);
            aF[3] = __float_as_uint(Ss[(m + 8) * AS_S + kb + fcol + 4]);
            #pragma unroll
            for (int nt = 0; nt < 4; nt++) {
                const int n = wn * 32 + nt * 8 + frow;
                uint32_t bF[2];
                bF[0] = __float_as_uint(Vs[(kb + fcol) * AQ_S + n]);
                bF[1] = __float_as_uint(Vs[(kb + fcol + 4) * AQ_S + n]);
                mma_tf32(oacc[nt], aF, bF);
            }
        }
        __syncthreads();
    }

    {
        const int qr = wm * 16 + frow;
        const float inv0 = 1.0f / l_s[qr], inv1 = 1.0f / l_s[qr + 8];
        #pragma unroll
        for (int nt = 0; nt < 4; nt++) {
            const int d = wn * 32 + nt * 8 + 2 * fcol;
            float2 o0; o0.x = oacc[nt][0] * inv0; o0.y = oacc[nt][1] * inv0;
            *(float2*)&Og[((size_t)b * NL + q0 + qr) * D_MODEL + h * DK + d] = o0;
            float2 o1; o1.x = oacc[nt][2] * inv1; o1.y = oacc[nt][3] * inv1;
            *(float2*)&Og[((size_t)b * NL + q0 + qr + 8) * D_MODEL + h * DK + d] = o1;
        }
    }
}

// ---------------- launch ----------------
extern "C" void kernel_launch(void* const* d_in, const int* in_sizes, int n_in,
                              void* d_out, int out_size)
{
    const float* src = (const float*)d_in[0];
    const float* sx  = (const float*)d_in[1];
    const float* sy  = (const float*)d_in[2];
    const float* Wq  = (const float*)d_in[3];
    const float* bq  = (const float*)d_in[4];
    const float* Wk  = (const float*)d_in[5];
    const float* bk  = (const float*)d_in[6];
    const float* Wv  = (const float*)d_in[7];
    const float* bv  = (const float*)d_in[8];
    const float* Wo  = (const float*)d_in[9];
    const float* bo  = (const float*)d_in[10];
    const float* P1  = (const float*)d_in[11];
    const float* pb1 = (const float*)d_in[12];
    const float* P2  = (const float*)d_in[13];
    const float* pb2 = (const float*)d_in[14];
    const float* W1  = (const float*)d_in[15];
    const float* b1  = (const float*)d_in[16];
    const float* W2  = (const float*)d_in[17];
    const float* b2  = (const float*)d_in[18];
    const float* g1  = (const float*)d_in[19];
    const float* be1 = (const float*)d_in[20];
    const float* g2  = (const float*)d_in[21];
    const float* be2 = (const float*)d_in[22];

    float* scratch = nullptr;
    cudaGetSymbolAddress((void**)&scratch, g_scratch);
    float* Q    = scratch + OFF_Q;
    float* K    = scratch + OFF_K;
    float* V    = scratch + OFF_V;
    float* Bias = scratch + OFF_BIAS;
    float* AO   = scratch + OFF_AO;
    float* X    = scratch + OFF_X;
    float* Hb   = scratch + OFF_H;
    float* PART = scratch + OFF_PART;

    cudaFuncSetAttribute(attn_kernel, cudaFuncAttributeMaxDynamicSharedMemorySize, ATTN_SMEM);
    cudaFuncSetAttribute(tgemm_kernel<MODE_QKV>, cudaFuncAttributeMaxDynamicSharedMemorySize, TG_SMEM);
    cudaFuncSetAttribute(tgemm_kernel<MODE_PART>, cudaFuncAttributeMaxDynamicSharedMemorySize, TG_SMEM);
    cudaFuncSetAttribute(tgemm_kernel<MODE_BIAS_RELU>, cudaFuncAttributeMaxDynamicSharedMemorySize, TG_SMEM);

    const int MN = MTOT * D_MODEL;

    // 1. fused QKV projection (tf32 tensor) -> (b,h,l,dk), Q pre-scaled
    tgemm_kernel<MODE_QKV><<<dim3(2304 / BN, MTOT / BM), 256, TG_SMEM>>>(
        src, Wq, Wk, Wv, bq, bk, bv, nullptr, Q, K, V, MTOT, 2304, D_MODEL, D_MODEL);

    // 2. relative-position bias
    bias_kernel<<<dim3(NL / 128, NL, NB), 128>>>(sx, sy, P1, pb1, P2, pb2, Bias);

    // 3. flash attention (tf32 tensor)
    attn_kernel<<<dim3(NL / 64, NHEAD, NB), 256, ATTN_SMEM>>>(Q, K, V, Bias, AO);

    // 4. output projection split-K=4 + fused reduce+bias+residual+LN1 -> X
    tgemm_kernel<MODE_PART><<<dim3(D_MODEL / BN, MTOT / BM, 4), 256, TG_SMEM>>>(
        AO, Wo, nullptr, nullptr, nullptr, nullptr, nullptr, nullptr,
        PART, nullptr, nullptr, MTOT, D_MODEL, 192, D_MODEL);
    reduce_ln_kernel<4><<<MTOT, 192>>>(PART, bo, src, g1, be1, X, MN);

    // 5. FFN up + ReLU
    tgemm_kernel<MODE_BIAS_RELU><<<dim3(FF / BN, MTOT / BM), 256, TG_SMEM>>>(
        X, W1, nullptr, nullptr, b1, nullptr, nullptr, nullptr, Hb, nullptr, nullptr,
        MTOT, FF, D_MODEL, D_MODEL);

    // 6. FFN down split-K=8 + fused reduce+bias+residual+LN2 -> out
    tgemm_kernel<MODE_PART><<<dim3(D_MODEL / BN, MTOT / BM, 8), 256, TG_SMEM>>>(
        Hb, W2, nullptr, nullptr, nullptr, nullptr, nullptr, nullptr,
        PART, nullptr, nullptr, MTOT, D_MODEL, 384, FF);
    reduce_ln_kernel<8><<<MTOT, 192>>>(PART, b2, X, g2, be2, (float*)d_out, MN);
}

// round 11
// speedup vs baseline: 1.1240x; 1.0035x over previous
#include <cuda_runtime.h>
#include <math.h>
#include <stddef.h>
#include <stdint.h>

#define D_MODEL 768
#define NHEAD 12
#define DK 64
#define FF 3072
#define NB 2
#define NL 1024
#define MTOT (NB*NL)   // 2048

// ---------------- scratch ----------------
#define OFF_Q    0
#define OFF_K    1572864
#define OFF_V    3145728
#define OFF_BIAS 4718592
#define OFF_AO   29884416
#define OFF_X    33030144
#define OFF_H    34603008
#define OFF_PART 42467328
#define SCRATCH_TOTAL (42467328 + 8*1572864)

__device__ float g_scratch[SCRATCH_TOTAL];

#define BM 128
#define BN 128

#define MODE_QKV 0
#define MODE_BIAS_RES 1
#define MODE_BIAS_RELU 2
#define MODE_PART 3

__device__ __forceinline__ uint32_t f2tf32(float x) {
    uint32_t r;
    asm("cvt.rna.tf32.f32 %0, %1;" : "=r"(r) : "f"(x));
    return r;
}
__device__ __forceinline__ float tf32f(float x) {
    return __uint_as_float(f2tf32(x));
}
__device__ __forceinline__ void mma_tf32(float* c, const uint32_t* a, const uint32_t* b) {
    asm volatile("mma.sync.aligned.m16n8k8.row.col.f32.tf32.tf32.f32 "
        "{%0,%1,%2,%3}, {%4,%5,%6,%7}, {%8,%9}, {%0,%1,%2,%3};"
        : "+f"(c[0]), "+f"(c[1]), "+f"(c[2]), "+f"(c[3])
        : "r"(a[0]), "r"(a[1]), "r"(a[2]), "r"(a[3]), "r"(b[0]), "r"(b[1]));
}
__device__ __forceinline__ void cp16(uint32_t dst, const float* src) {
    asm volatile("cp.async.cg.shared.global [%0], [%1], 16;" :: "r"(dst), "l"(src));
}
#define CP_COMMIT() asm volatile("cp.async.commit_group;")
template<int N> __device__ __forceinline__ void cp_wait() {
    asm volatile("cp.async.wait_group %0;" :: "n"(N));
}

// FMA-pipe exp for x <= 0: magic-number round-to-int + Taylor(6) + exponent inject.
// Avoids MUFU entirely (attention softmax is MUFU-throughput-bound otherwise).
__device__ __forceinline__ float fast_exp(float x) {
    x = fmaxf(x, -80.0f);
    float z = fmaf(x, 1.4426950408889634f, 12582912.0f);   // n in low mantissa bits
    float n = z - 12582912.0f;
    float r = fmaf(n, -0.693359375f, x);                    // x - n*ln2_hi
    r = fmaf(n, 2.12194440e-4f, r);                         // - n*ln2_lo
    float p = 1.3888889e-3f;                                // 1/720
    p = fmaf(p, r, 8.3333333e-3f);                          // 1/120
    p = fmaf(p, r, 4.1666668e-2f);                          // 1/24
    p = fmaf(p, r, 1.6666667e-1f);                          // 1/6
    p = fmaf(p, r, 0.5f);
    p = fmaf(p, r, 1.0f);
    p = fmaf(p, r, 1.0f);
    return __int_as_float(__float_as_int(p) + (__float_as_int(z) << 23));
}

// ---------------- tensor-core GEMM: 128x128x16 tiles, cp.async 3-stage ----------------
#define ASTR 20
#define BSTR 136
#define SSTRIDE 4736
#define TG_SMEM (3 * SSTRIDE * 4)

template<int MODE>
__global__ __launch_bounds__(256, 2)
void tgemm_kernel(const float* __restrict__ A,
                  const float* __restrict__ B0, const float* __restrict__ B1, const float* __restrict__ B2,
                  const float* __restrict__ bias0, const float* __restrict__ bias1, const float* __restrict__ bias2,
                  const float* __restrict__ R,
                  float* __restrict__ C0, float* __restrict__ C1, float* __restrict__ C2,
                  int M, int N, int K, int lda)
{
    extern __shared__ float smem[];
    const uint32_t smem_u32 = (uint32_t)__cvta_generic_to_shared(smem);

    const int bx = blockIdx.x, by = blockIdx.y;
    const int tid = threadIdx.x;

    const float* Asrc = A;
    const float* Bsel = B0;
    const float* bsel = bias0;
    size_t outoff = 0;
    int ncol0 = bx * BN;
    int Nw = N;
    int region = 0;
    if (MODE == MODE_QKV) {
        region = ncol0 / 768;
        Bsel = (region == 0) ? B0 : (region == 1 ? B1 : B2);
        bsel = (region == 0) ? bias0 : (region == 1 ? bias1 : bias2);
        ncol0 -= region * 768;
        Nw = 768;
    }
    if (MODE == MODE_PART) {
        const int z = blockIdx.z;
        Asrc = A + (size_t)z * K;
        Bsel = B0 + (size_t)z * K * N;
        outoff = (size_t)z * ((size_t)M * N);
    }

    const int lmA = tid >> 1, lk8 = (tid & 1) * 8;
    const int lkB = tid >> 5, ln4 = (tid & 31) * 4;
    const float* ApBase = Asrc + (size_t)(by * BM + lmA) * lda + lk8;
    const float* BpBase = Bsel + (size_t)lkB * Nw + ncol0 + ln4;

    const int NK = K / 16;

    const int lane = tid & 31, warp = tid >> 5;
    const int wm = warp >> 1, wn = warp & 1;
    const int frow = lane >> 2, fcol = lane & 3;

    float acc[2][8][4];
    #pragma unroll
    for (int i = 0; i < 2; i++)
        #pragma unroll
        for (int j = 0; j < 8; j++)
            #pragma unroll
            for (int r = 0; r < 4; r++) acc[i][j][r] = 0.0f;

    auto load_stage = [&](int kt, int s) {
        if (kt < NK) {
            const int k0 = kt * 16;
            const uint32_t sa = smem_u32 + (uint32_t)(s * SSTRIDE) * 4;
            const uint32_t sb = sa + 2560 * 4;
            const float* srcA = ApBase + k0;
            cp16(sa + (uint32_t)(lmA * ASTR + lk8) * 4, srcA);
            cp16(sa + (uint32_t)(lmA * ASTR + lk8 + 4) * 4, srcA + 4);
            const float* srcB = BpBase + (size_t)k0 * Nw;
            cp16(sb + (uint32_t)(lkB * BSTR + ln4) * 4, srcB);
            cp16(sb + (uint32_t)((lkB + 8) * BSTR + ln4) * 4, srcB + (size_t)8 * Nw);
        }
        CP_COMMIT();
    };

    load_stage(0, 0);
    load_stage(1, 1);

    int buf = 0;
    for (int kt = 0; kt < NK; kt++) {
        cp_wait<1>();
        __syncthreads();

        int nbuf = buf + 2; if (nbuf >= 3) nbuf -= 3;
        load_stage(kt + 2, nbuf);

        const float* As_ = smem + buf * SSTRIDE;
        const float* Bs_ = smem + buf * SSTRIDE + 2560;

        #pragma unroll
        for (int ks = 0; ks < 2; ks++) {
            const int kb = ks * 8;
            uint32_t aF[2][4], bF[8][2];
            #pragma unroll
            for (int mt = 0; mt < 2; mt++) {
                const int m = wm * 32 + mt * 16 + frow;
                aF[mt][0] = __float_as_uint(As_[m * ASTR + kb + fcol]);
                aF[mt][1] = __float_as_uint(As_[(m + 8) * ASTR + kb + fcol]);
                aF[mt][2] = __float_as_uint(As_[m * ASTR + kb + fcol + 4]);
                aF[mt][3] = __float_as_uint(As_[(m + 8) * ASTR + kb + fcol + 4]);
            }
            #pragma unroll
            for (int nt = 0; nt < 8; nt++) {
                const int n = wn * 64 + nt * 8 + frow;
                bF[nt][0] = __float_as_uint(Bs_[(kb + fcol) * BSTR + n]);
                bF[nt][1] = __float_as_uint(Bs_[(kb + fcol + 4) * BSTR + n]);
            }
            #pragma unroll
            for (int mt = 0; mt < 2; mt++)
                #pragma unroll
                for (int nt = 0; nt < 8; nt++)
                    mma_tf32(acc[mt][nt], aF[mt], bF[nt]);
        }

        buf = buf + 1; if (buf >= 3) buf -= 3;
    }

    if (MODE == MODE_QKV) {
        float* dst = (region == 0) ? C0 : (region == 1 ? C1 : C2);
        const float scale = (region == 0) ? 0.125f : 1.0f;
        #pragma unroll
        for (int mt = 0; mt < 2; mt++)
            #pragma unroll
            for (int nt = 0; nt < 8; nt++) {
                const int n = ncol0 + wn * 64 + nt * 8 + 2 * fcol;
                const int h = n >> 6, d = n & 63;
                const float bv0 = bsel[n], bv1 = bsel[n + 1];
                #pragma unroll
                for (int half = 0; half < 2; half++) {
                    const int m = by * BM + wm * 32 + mt * 16 + frow + half * 8;
                    const int b = m >> 10, l = m & 1023;
                    float2 o;
                    o.x = (acc[mt][nt][half * 2 + 0] + bv0) * scale;
                    o.y = (acc[mt][nt][half * 2 + 1] + bv1) * scale;
                    *(float2*)&dst[((((size_t)b * NHEAD + h) << 10) + l) * DK + d] = o;
                }
            }
    } else if (MODE == MODE_PART) {
        #pragma unroll
        for (int mt = 0; mt < 2; mt++)
            #pragma unroll
            for (int nt = 0; nt < 8; nt++) {
                const int n = ncol0 + wn * 64 + nt * 8 + 2 * fcol;
                #pragma unroll
                for (int half = 0; half < 2; half++) {
                    const int m = by * BM + wm * 32 + mt * 16 + frow + half * 8;
                    float2 o;
                    o.x = acc[mt][nt][half * 2 + 0];
                    o.y = acc[mt][nt][half * 2 + 1];
                    *(float2*)&C0[outoff + (size_t)m * N + n] = o;
                }
            }
    } else {
        #pragma unroll
        for (int mt = 0; mt < 2; mt++)
            #pragma unroll
            for (int nt = 0; nt < 8; nt++) {
                const int n = ncol0 + wn * 64 + nt * 8 + 2 * fcol;
                const float bv0 = bias0[n], bv1 = bias0[n + 1];
                #pragma unroll
                for (int half = 0; half < 2; half++) {
                    const int m = by * BM + wm * 32 + mt * 16 + frow + half * 8;
                    float vx = acc[mt][nt][half * 2 + 0] + bv0;
                    float vy = acc[mt][nt][half * 2 + 1] + bv1;
                    if (MODE == MODE_BIAS_RES) {
                        const float* rp = R + (size_t)m * N + n;
                        vx += rp[0]; vy += rp[1];
                    } else {
                        vx = fmaxf(vx, 0.0f); vy = fmaxf(vy, 0.0f);
                    }
                    float2 o; o.x = vx; o.y = vy;
                    *(float2*)&C0[(size_t)m * N + n] = o;
                }
            }
    }
}

// ---------------- fused split-K reduce + bias + residual + LayerNorm ----------------
template<int SPLITK>
__global__ __launch_bounds__(192)
void reduce_ln_kernel(const float* __restrict__ P, const float* __restrict__ bias,
                      const float* __restrict__ R, const float* __restrict__ gam,
                      const float* __restrict__ bet, float* __restrict__ Y, int MN)
{
    const int row = blockIdx.x;
    const int t = threadIdx.x;
    const int col = t * 4;
    const size_t i = (size_t)row * D_MODEL + col;

    float4 s = *(const float4*)(P + i);
    #pragma unroll
    for (int z = 1; z < SPLITK; z++) {
        float4 p = *(const float4*)(P + (size_t)z * MN + i);
        s.x += p.x; s.y += p.y; s.z += p.z; s.w += p.w;
    }
    float4 bv = *(const float4*)(bias + col);
    float4 rv = *(const float4*)(R + i);
    s.x += bv.x + rv.x;
    s.y += bv.y + rv.y;
    s.z += bv.z + rv.z;
    s.w += bv.w + rv.w;

    float a  = s.x + s.y + s.z + s.w;
    float q  = s.x * s.x + s.y * s.y + s.z * s.z + s.w * s.w;
    #pragma unroll
    for (int o = 16; o; o >>= 1) {
        a += __shfl_down_sync(0xffffffffu, a, o);
        q += __shfl_down_sync(0xffffffffu, q, o);
    }
    __shared__ float sm0[6], sm1[6], bcast[2];
    const int wid = t >> 5, lanei = t & 31;
    if (lanei == 0) { sm0[wid] = a; sm1[wid] = q; }
    __syncthreads();
    if (t == 0) {
        float ta = 0.0f, tq = 0.0f;
        #pragma unroll
        for (int w = 0; w < 6; w++) { ta += sm0[w]; tq += sm1[w]; }
        const float mean = ta * (1.0f / D_MODEL);
        const float var  = tq * (1.0f / D_MODEL) - mean * mean;
        bcast[0] = mean;
        bcast[1] = rsqrtf(var + 1e-5f);
    }
    __syncthreads();
    const float mean = bcast[0], inv = bcast[1];

    float4 gv = *(const float4*)(gam + col);
    float4 ev = *(const float4*)(bet + col);
    float4 y;
    y.x = (s.x - mean) * inv * gv.x + ev.x;
    y.y = (s.y - mean) * inv * gv.y + ev.y;
    y.z = (s.z - mean) * inv * gv.z + ev.z;
    y.w = (s.w - mean) * inv * gv.w + ev.w;
    *(float4*)(Y + i) = y;
}

// ---------------- relative-position bias MLP ----------------
__global__ __launch_bounds__(128)
void bias_kernel(const float* __restrict__ sx, const float* __restrict__ sy,
                 const float* __restrict__ P1, const float* __restrict__ pb1,
                 const float* __restrict__ P2, const float* __restrict__ pb2,
                 float* __restrict__ gbias)
{
    __shared__ float sP1[64], spb1[32], sP2[384], spb2[12];
    const int tid = threadIdx.x;
    if (tid < 64) sP1[tid] = P1[tid];
    if (tid < 32) spb1[tid] = pb1[tid];
    if (tid < 12) spb2[tid] = pb2[tid];
    for (int i = tid; i < 384; i += 128) sP2[i] = P2[i];
    __syncthreads();

    const int k = blockIdx.x * 128 + tid;
    const int q = blockIdx.y;
    const int b = blockIdx.z;

    const float xq = sx[b * NL + q], yq = sy[b * NL + q];
    float rx = fminf(fmaxf(xq - sx[b * NL + k], -1000.0f), 1000.0f) * 0.001f;
    float ry = fminf(fmaxf(yq - sy[b * NL + k], -1000.0f), 1000.0f) * 0.001f;

    float hbuf[32];
    #pragma unroll
    for (int j = 0; j < 32; j++) {
        float v = fmaf(rx, sP1[j], fmaf(ry, sP1[32 + j], spb1[j]));
        hbuf[j] = fmaxf(v, 0.0f);
    }
    #pragma unroll
    for (int h = 0; h < NHEAD; h++) {
        float s = spb2[h];
        #pragma unroll
        for (int j = 0; j < 32; j++) s = fmaf(hbuf[j], sP2[j * NHEAD + h], s);
        gbias[((((size_t)b * NHEAD + h) << 10) + q) * NL + k] = s;
    }
}

// ---------------- flash attention: tf32 mma, 64x64 tiles ----------------
#define AQ_S 72
#define AS_S 68
#define AT_KS (64*AQ_S)
#define AT_VS (2*64*AQ_S)
#define AT_SS (3*64*AQ_S)
#define ATTN_SMEM ((3*64*AQ_S + 64*AS_S)*4)

__global__ __launch_bounds__(256)
void attn_kernel(const float* __restrict__ Qg, const float* __restrict__ Kg,
                 const float* __restrict__ Vg, const float* __restrict__ biasg,
                 float* __restrict__ Og)
{
    extern __shared__ float smem[];
    float* Qs = smem;
    float* Ks = smem + AT_KS;
    float* Vs = smem + AT_VS;
    float* Ss = smem + AT_SS;
    __shared__ float m_s[64], l_s[64], cf_s[64];

    const int b = blockIdx.z, h = blockIdx.y, q0 = blockIdx.x * 64;
    const int bh = b * NHEAD + h;
    const int tid = threadIdx.x;
    const int lane = tid & 31, warp = tid >> 5;
    const int wm = warp >> 1, wn = warp & 1;
    const int frow = lane >> 2, fcol = lane & 3;

    {
        const int r = tid >> 2;
        const int d4 = (tid & 3) * 16;
        const float* qp = Qg + (((size_t)bh << 10) + q0 + r) * DK + d4;
        #pragma unroll
        for (int t = 0; t < 4; t++) {
            float4 v = *(const float4*)(qp + t * 4);
            const int d = d4 + t * 4;
            Qs[(d + 0) * AQ_S + r] = tf32f(v.x);
            Qs[(d + 1) * AQ_S + r] = tf32f(v.y);
            Qs[(d + 2) * AQ_S + r] = tf32f(v.z);
            Qs[(d + 3) * AQ_S + r] = tf32f(v.w);
        }
    }
    if (tid < 64) { m_s[tid] = -1e30f; l_s[tid] = 0.0f; }

    float oacc[4][4];
    #pragma unroll
    for (int i = 0; i < 4; i++)
        #pragma unroll
        for (int j = 0; j < 4; j++) oacc[i][j] = 0.0f;

    __syncthreads();

    for (int kt = 0; kt < 16; kt++) {
        const int k0 = kt * 64;
        {
            const int r = tid >> 2;
            const int d4 = (tid & 3) * 16;
            const float* kp = Kg + (((size_t)bh << 10) + k0 + r) * DK + d4;
            const float* vp = Vg + (((size_t)bh << 10) + k0 + r) * DK + d4;
            #pragma unroll
            for (int t = 0; t < 4; t++) {
                float4 kv = *(const float4*)(kp + t * 4);
                const int d = d4 + t * 4;
                Ks[(d + 0) * AQ_S + r] = tf32f(kv.x);
                Ks[(d + 1) * AQ_S + r] = tf32f(kv.y);
                Ks[(d + 2) * AQ_S + r] = tf32f(kv.z);
                Ks[(d + 3) * AQ_S + r] = tf32f(kv.w);
                float4 vv = *(const float4*)(vp + t * 4);
                float4 vc = make_float4(tf32f(vv.x), tf32f(vv.y), tf32f(vv.z), tf32f(vv.w));
                *(float4*)&Vs[r * AQ_S + d] = vc;
            }
        }
        __syncthreads();

        float sacc[4][4];
        #pragma unroll
        for (int i = 0; i < 4; i++)
            #pragma unroll
            for (int j = 0; j < 4; j++) sacc[i][j] = 0.0f;

        const int m = wm * 16 + frow;
        #pragma unroll
        for (int ks = 0; ks < 8; ks++) {
            const int kb = ks * 8;
            uint32_t aF[4];
            aF[0] = __float_as_uint(Qs[(kb + fcol) * AQ_S + m]);
            aF[1] = __float_as_uint(Qs[(kb + fcol) * AQ_S + m + 8]);
            aF[2] = __float_as_uint(Qs[(kb + fcol + 4) * AQ_S + m]);
            aF[3] = __float_as_uint(Qs[(kb + fcol + 4) * AQ_S + m + 8]);
            #pragma unroll
            for (int nt = 0; nt < 4; nt++) {
                const int n = wn * 32 + nt * 8 + frow;
                uint32_t bF[2];
                bF[0] = __float_as_uint(Ks[(kb + fcol) * AQ_S + n]);
                bF[1] = __float_as_uint(Ks[(kb + fcol + 4) * AQ_S + n]);
                mma_tf32(sacc[nt], aF, bF);
            }
        }

        #pragma unroll
        for (int nt = 0; nt < 4; nt++) {
            const int c = wn * 32 + nt * 8 + 2 * fcol;
            const int qr = wm * 16 + frow;
            const float* bp0 = biasg + ((((size_t)bh << 10) + q0 + qr) << 10) + k0 + c;
            float2 bv0 = *(const float2*)bp0;
            Ss[qr * AS_S + c]     = sacc[nt][0] + bv0.x;
            Ss[qr * AS_S + c + 1] = sacc[nt][1] + bv0.y;
            const float* bp1 = biasg + ((((size_t)bh << 10) + q0 + qr + 8) << 10) + k0 + c;
            float2 bv1 = *(const float2*)bp1;
            Ss[(qr + 8) * AS_S + c]     = sacc[nt][2] + bv1.x;
            Ss[(qr + 8) * AS_S + c + 1] = sacc[nt][3] + bv1.y;
        }
        __syncthreads();

        {
            const int r = tid >> 2;
            float* srow = &Ss[r * AS_S + (tid & 3) * 16];
            const float mold = m_s[r];
            float mx = -1e30f;
            #pragma unroll
            for (int c = 0; c < 16; c++) mx = fmaxf(mx, srow[c]);
            mx = fmaxf(mx, __shfl_xor_sync(0xffffffffu, mx, 1));
            mx = fmaxf(mx, __shfl_xor_sync(0xffffffffu, mx, 2));
            mx = fmaxf(mx, mold);
            float sum = 0.0f;
            #pragma unroll
            for (int c = 0; c < 16; c++) {
                float p = tf32f(fast_exp(srow[c] - mx));
                srow[c] = p;
                sum += p;
            }
            sum += __shfl_xor_sync(0xffffffffu, sum, 1);
            sum += __shfl_xor_sync(0xffffffffu, sum, 2);
            if ((tid & 3) == 0) {
                float cf = fast_exp(mold - mx);
                l_s[r] = l_s[r] * cf + sum;
                m_s[r] = mx;
                cf_s[r] = cf;
            }
        }
        __syncthreads();

        {
            const int qr = wm * 16 + frow;
            const float cf0 = cf_s[qr], cf1 = cf_s[qr + 8];
            #pragma unroll
            for (int nt = 0; nt < 4; nt++) {
                oacc[nt][0] *= cf0; oacc[nt][1] *= cf0;
                oacc[nt][2] *= cf1; oacc[nt][3] *= cf1;
            }
        }
        #pragma unroll
        for (int ks = 0; ks < 8; ks++) {
            const int kb = ks * 8;
            uint32_t aF[4];
            aF[0] = __float_as_uint(Ss[m * AS_S + kb + fcol]);
            aF[1] = __float_as_uint(Ss[(m + 8) * AS_S + kb + fcol]);
            aF[2] = __float_as_uint(Ss[m * AS_S + kb + fcol + 4]);
            aF[3] = __float_as_uint(Ss[(m + 8) * AS_S + kb + fcol + 4]);
            #pragma unroll
            for (int nt = 0; nt < 4; nt++) {
                const int n = wn * 32 + nt * 8 + frow;
                uint32_t bF[2];
                bF[0] = __float_as_uint(Vs[(kb + fcol) * AQ_S + n]);
                bF[1] = __float_as_uint(Vs[(kb + fcol + 4) * AQ_S + n]);
                mma_tf32(oacc[nt], aF, bF);
            }
        }
        __syncthreads();
    }

    {
        const int qr = wm * 16 + frow;
        const float inv0 = 1.0f / l_s[qr], inv1 = 1.0f / l_s[qr + 8];
        #pragma unroll
        for (int nt = 0; nt < 4; nt++) {
            const int d = wn * 32 + nt * 8 + 2 * fcol;
            float2 o0; o0.x = oacc[nt][0] * inv0; o0.y = oacc[nt][1] * inv0;
            *(float2*)&Og[((size_t)b * NL + q0 + qr) * D_MODEL + h * DK + d] = o0;
            float2 o1; o1.x = oacc[nt][2] * inv1; o1.y = oacc[nt][3] * inv1;
            *(float2*)&Og[((size_t)b * NL + q0 + qr + 8) * D_MODEL + h * DK + d] = o1;
        }
    }
}

// ---------------- launch ----------------
extern "C" void kernel_launch(void* const* d_in, const int* in_sizes, int n_in,
                              void* d_out, int out_size)
{
    const float* src = (const float*)d_in[0];
    const float* sx  = (const float*)d_in[1];
    const float* sy  = (const float*)d_in[2];
    const float* Wq  = (const float*)d_in[3];
    const float* bq  = (const float*)d_in[4];
    const float* Wk  = (const float*)d_in[5];
    const float* bk  = (const float*)d_in[6];
    const float* Wv  = (const float*)d_in[7];
    const float* bv  = (const float*)d_in[8];
    const float* Wo  = (const float*)d_in[9];
    const float* bo  = (const float*)d_in[10];
    const float* P1  = (const float*)d_in[11];
    const float* pb1 = (const float*)d_in[12];
    const float* P2  = (const float*)d_in[13];
    const float* pb2 = (const float*)d_in[14];
    const float* W1  = (const float*)d_in[15];
    const float* b1  = (const float*)d_in[16];
    const float* W2  = (const float*)d_in[17];
    const float* b2  = (const float*)d_in[18];
    const float* g1  = (const float*)d_in[19];
    const float* be1 = (const float*)d_in[20];
    const float* g2  = (const float*)d_in[21];
    const float* be2 = (const float*)d_in[22];

    float* scratch = nullptr;
    cudaGetSymbolAddress((void**)&scratch, g_scratch);
    float* Q    = scratch + OFF_Q;
    float* K    = scratch + OFF_K;
    float* V    = scratch + OFF_V;
    float* Bias = scratch + OFF_BIAS;
    float* AO   = scratch + OFF_AO;
    float* X    = scratch + OFF_X;
    float* Hb   = scratch + OFF_H;
    float* PART = scratch + OFF_PART;

    cudaFuncSetAttribute(attn_kernel, cudaFuncAttributeMaxDynamicSharedMemorySize, ATTN_SMEM);
    cudaFuncSetAttribute(tgemm_kernel<MODE_QKV>, cudaFuncAttributeMaxDynamicSharedMemorySize, TG_SMEM);
    cudaFuncSetAttribute(tgemm_kernel<MODE_PART>, cudaFuncAttributeMaxDynamicSharedMemorySize, TG_SMEM);
    cudaFuncSetAttribute(tgemm_kernel<MODE_BIAS_RELU>, cudaFuncAttributeMaxDynamicSharedMemorySize, TG_SMEM);

    const int MN = MTOT * D_MODEL;

    // 1. fused QKV projection (tf32 tensor) -> (b,h,l,dk), Q pre-scaled
    tgemm_kernel<MODE_QKV><<<dim3(2304 / BN, MTOT / BM), 256, TG_SMEM>>>(
        src, Wq, Wk, Wv, bq, bk, bv, nullptr, Q, K, V, MTOT, 2304, D_MODEL, D_MODEL);

    // 2. relative-position bias
    bias_kernel<<<dim3(NL / 128, NL, NB), 128>>>(sx, sy, P1, pb1, P2, pb2, Bias);

    // 3. flash attention (tf32 tensor, FMA-pipe exp)
    attn_kernel<<<dim3(NL / 64, NHEAD, NB), 256, ATTN_SMEM>>>(Q, K, V, Bias, AO);

    // 4. output projection split-K=4 + fused reduce+bias+residual+LN1 -> X
    tgemm_kernel<MODE_PART><<<dim3(D_MODEL / BN, MTOT / BM, 4), 256, TG_SMEM>>>(
        AO, Wo, nullptr, nullptr, nullptr, nullptr, nullptr, nullptr,
        PART, nullptr, nullptr, MTOT, D_MODEL, 192, D_MODEL);
    reduce_ln_kernel<4><<<MTOT, 192>>>(PART, bo, src, g1, be1, X, MN);

    // 5. FFN up + ReLU
    tgemm_kernel<MODE_BIAS_RELU><<<dim3(FF / BN, MTOT / BM), 256, TG_SMEM>>>(
        X, W1, nullptr, nullptr, b1, nullptr, nullptr, nullptr, Hb, nullptr, nullptr,
        MTOT, FF, D_MODEL, D_MODEL);

    // 6. FFN down split-K=8 + fused reduce+bias+residual+LN2 -> out
    tgemm_kernel<MODE_PART><<<dim3(D_MODEL / BN, MTOT / BM, 8), 256, TG_SMEM>>>(
        Hb, W2, nullptr, nullptr, nullptr, nullptr, nullptr, nullptr,
        PART, nullptr, nullptr, MTOT, D_MODEL, 384, FF);
    reduce_ln_kernel<8><<<MTOT, 192>>>(PART, b2, X, g2, be2, (float*)d_out, MN);
}

// round 13
// speedup vs baseline: 1.1311x; 1.0063x over previous
#include <cuda_runtime.h>
#include <math.h>
#include <stddef.h>
#include <stdint.h>

#define D_MODEL 768
#define NHEAD 12
#define DK 64
#define FF 3072
#define NB 2
#define NL 1024
#define MTOT (NB*NL)   // 2048

// ---------------- scratch ----------------
#define OFF_Q    0
#define OFF_K    1572864
#define OFF_V    3145728
#define OFF_BIAS 4718592
#define OFF_AO   29884416
#define OFF_X    33030144
#define OFF_H    34603008
#define OFF_PART 42467328
#define SCRATCH_TOTAL (42467328 + 8*1572864)

__device__ float g_scratch[SCRATCH_TOTAL];

#define BM 128
#define BN 128

#define MODE_QKV 0
#define MODE_BIAS_RES 1
#define MODE_BIAS_RELU 2
#define MODE_PART 3

__device__ __forceinline__ uint32_t f2tf32(float x) {
    uint32_t r;
    asm("cvt.rna.tf32.f32 %0, %1;" : "=r"(r) : "f"(x));
    return r;
}
__device__ __forceinline__ float tf32f(float x) {
    return __uint_as_float(f2tf32(x));
}
__device__ __forceinline__ void mma_tf32(float* c, const uint32_t* a, const uint32_t* b) {
    asm volatile("mma.sync.aligned.m16n8k8.row.col.f32.tf32.tf32.f32 "
        "{%0,%1,%2,%3}, {%4,%5,%6,%7}, {%8,%9}, {%0,%1,%2,%3};"
        : "+f"(c[0]), "+f"(c[1]), "+f"(c[2]), "+f"(c[3])
        : "r"(a[0]), "r"(a[1]), "r"(a[2]), "r"(a[3]), "r"(b[0]), "r"(b[1]));
}
__device__ __forceinline__ void cp16(uint32_t dst, const float* src) {
    asm volatile("cp.async.cg.shared.global [%0], [%1], 16;" :: "r"(dst), "l"(src));
}
#define CP_COMMIT() asm volatile("cp.async.commit_group;")
template<int N> __device__ __forceinline__ void cp_wait() {
    asm volatile("cp.async.wait_group %0;" :: "n"(N));
}

// FMA-pipe exp for x <= 0 (keeps MUFU free; cheap enough either way).
__device__ __forceinline__ float fast_exp(float x) {
    x = fmaxf(x, -80.0f);
    float z = fmaf(x, 1.4426950408889634f, 12582912.0f);
    float n = z - 12582912.0f;
    float r = fmaf(n, -0.693359375f, x);
    r = fmaf(n, 2.12194440e-4f, r);
    float p = 1.3888889e-3f;
    p = fmaf(p, r, 8.3333333e-3f);
    p = fmaf(p, r, 4.1666668e-2f);
    p = fmaf(p, r, 1.6666667e-1f);
    p = fmaf(p, r, 0.5f);
    p = fmaf(p, r, 1.0f);
    p = fmaf(p, r, 1.0f);
    return __int_as_float(__float_as_int(p) + (__float_as_int(z) << 23));
}

// ---------------- tensor-core GEMM: 128x128x16 tiles, cp.async 3-stage ----------------
#define ASTR 20
#define BSTR 136
#define SSTRIDE 4736
#define TG_SMEM (3 * SSTRIDE * 4)

template<int MODE>
__global__ __launch_bounds__(256, 2)
void tgemm_kernel(const float* __restrict__ A,
                  const float* __restrict__ B0, const float* __restrict__ B1, const float* __restrict__ B2,
                  const float* __restrict__ bias0, const float* __restrict__ bias1, const float* __restrict__ bias2,
                  const float* __restrict__ R,
                  float* __restrict__ C0, float* __restrict__ C1, float* __restrict__ C2,
                  int M, int N, int K, int lda)
{
    extern __shared__ float smem[];
    const uint32_t smem_u32 = (uint32_t)__cvta_generic_to_shared(smem);

    const int bx = blockIdx.x, by = blockIdx.y;
    const int tid = threadIdx.x;

    const float* Asrc = A;
    const float* Bsel = B0;
    const float* bsel = bias0;
    size_t outoff = 0;
    int ncol0 = bx * BN;
    int Nw = N;
    int region = 0;
    if (MODE == MODE_QKV) {
        region = ncol0 / 768;
        Bsel = (region == 0) ? B0 : (region == 1 ? B1 : B2);
        bsel = (region == 0) ? bias0 : (region == 1 ? bias1 : bias2);
        ncol0 -= region * 768;
        Nw = 768;
    }
    if (MODE == MODE_PART) {
        const int z = blockIdx.z;
        Asrc = A + (size_t)z * K;
        Bsel = B0 + (size_t)z * K * N;
        outoff = (size_t)z * ((size_t)M * N);
    }

    const int lmA = tid >> 1, lk8 = (tid & 1) * 8;
    const int lkB = tid >> 5, ln4 = (tid & 31) * 4;
    const float* ApBase = Asrc + (size_t)(by * BM + lmA) * lda + lk8;
    const float* BpBase = Bsel + (size_t)lkB * Nw + ncol0 + ln4;

    const int NK = K / 16;

    const int lane = tid & 31, warp = tid >> 5;
    const int wm = warp >> 1, wn = warp & 1;
    const int frow = lane >> 2, fcol = lane & 3;

    float acc[2][8][4];
    #pragma unroll
    for (int i = 0; i < 2; i++)
        #pragma unroll
        for (int j = 0; j < 8; j++)
            #pragma unroll
            for (int r = 0; r < 4; r++) acc[i][j][r] = 0.0f;

    auto load_stage = [&](int kt, int s) {
        if (kt < NK) {
            const int k0 = kt * 16;
            const uint32_t sa = smem_u32 + (uint32_t)(s * SSTRIDE) * 4;
            const uint32_t sb = sa + 2560 * 4;
            const float* srcA = ApBase + k0;
            cp16(sa + (uint32_t)(lmA * ASTR + lk8) * 4, srcA);
            cp16(sa + (uint32_t)(lmA * ASTR + lk8 + 4) * 4, srcA + 4);
            const float* srcB = BpBase + (size_t)k0 * Nw;
            cp16(sb + (uint32_t)(lkB * BSTR + ln4) * 4, srcB);
            cp16(sb + (uint32_t)((lkB + 8) * BSTR + ln4) * 4, srcB + (size_t)8 * Nw);
        }
        CP_COMMIT();
    };

    load_stage(0, 0);
    load_stage(1, 1);

    int buf = 0;
    for (int kt = 0; kt < NK; kt++) {
        cp_wait<1>();
        __syncthreads();

        int nbuf = buf + 2; if (nbuf >= 3) nbuf -= 3;
        load_stage(kt + 2, nbuf);

        const float* As_ = smem + buf * SSTRIDE;
        const float* Bs_ = smem + buf * SSTRIDE + 2560;

        #pragma unroll
        for (int ks = 0; ks < 2; ks++) {
            const int kb = ks * 8;
            uint32_t aF[2][4], bF[8][2];
            #pragma unroll
            for (int mt = 0; mt < 2; mt++) {
                const int m = wm * 32 + mt * 16 + frow;
                aF[mt][0] = __float_as_uint(As_[m * ASTR + kb + fcol]);
                aF[mt][1] = __float_as_uint(As_[(m + 8) * ASTR + kb + fcol]);
                aF[mt][2] = __float_as_uint(As_[m * ASTR + kb + fcol + 4]);
                aF[mt][3] = __float_as_uint(As_[(m + 8) * ASTR + kb + fcol + 4]);
            }
            #pragma unroll
            for (int nt = 0; nt < 8; nt++) {
                const int n = wn * 64 + nt * 8 + frow;
                bF[nt][0] = __float_as_uint(Bs_[(kb + fcol) * BSTR + n]);
                bF[nt][1] = __float_as_uint(Bs_[(kb + fcol + 4) * BSTR + n]);
            }
            #pragma unroll
            for (int mt = 0; mt < 2; mt++)
                #pragma unroll
                for (int nt = 0; nt < 8; nt++)
                    mma_tf32(acc[mt][nt], aF[mt], bF[nt]);
        }

        buf = buf + 1; if (buf >= 3) buf -= 3;
    }

    if (MODE == MODE_QKV) {
        float* dst = (region == 0) ? C0 : (region == 1 ? C1 : C2);
        const float scale = (region == 0) ? 0.125f : 1.0f;
        #pragma unroll
        for (int mt = 0; mt < 2; mt++)
            #pragma unroll
            for (int nt = 0; nt < 8; nt++) {
                const int n = ncol0 + wn * 64 + nt * 8 + 2 * fcol;
                const int h = n >> 6, d = n & 63;
                const float bv0 = bsel[n], bv1 = bsel[n + 1];
                #pragma unroll
                for (int half = 0; half < 2; half++) {
                    const int m = by * BM + wm * 32 + mt * 16 + frow + half * 8;
                    const int b = m >> 10, l = m & 1023;
                    float2 o;
                    o.x = (acc[mt][nt][half * 2 + 0] + bv0) * scale;
                    o.y = (acc[mt][nt][half * 2 + 1] + bv1) * scale;
                    *(float2*)&dst[((((size_t)b * NHEAD + h) << 10) + l) * DK + d] = o;
                }
            }
    } else if (MODE == MODE_PART) {
        #pragma unroll
        for (int mt = 0; mt < 2; mt++)
            #pragma unroll
            for (int nt = 0; nt < 8; nt++) {
                const int n = ncol0 + wn * 64 + nt * 8 + 2 * fcol;
                #pragma unroll
                for (int half = 0; half < 2; half++) {
                    const int m = by * BM + wm * 32 + mt * 16 + frow + half * 8;
                    float2 o;
                    o.x = acc[mt][nt][half * 2 + 0];
                    o.y = acc[mt][nt][half * 2 + 1];
                    *(float2*)&C0[outoff + (size_t)m * N + n] = o;
                }
            }
    } else {
        #pragma unroll
        for (int mt = 0; mt < 2; mt++)
            #pragma unroll
            for (int nt = 0; nt < 8; nt++) {
                const int n = ncol0 + wn * 64 + nt * 8 + 2 * fcol;
                const float bv0 = bias0[n], bv1 = bias0[n + 1];
                #pragma unroll
                for (int half = 0; half < 2; half++) {
                    const int m = by * BM + wm * 32 + mt * 16 + frow + half * 8;
                    float vx = acc[mt][nt][half * 2 + 0] + bv0;
                    float vy = acc[mt][nt][half * 2 + 1] + bv1;
                    if (MODE == MODE_BIAS_RES) {
                        const float* rp = R + (size_t)m * N + n;
                        vx += rp[0]; vy += rp[1];
                    } else {
                        vx = fmaxf(vx, 0.0f); vy = fmaxf(vy, 0.0f);
                    }
                    float2 o; o.x = vx; o.y = vy;
                    *(float2*)&C0[(size_t)m * N + n] = o;
                }
            }
    }
}

// ---------------- fused split-K reduce + bias + residual + LayerNorm ----------------
template<int SPLITK>
__global__ __launch_bounds__(192)
void reduce_ln_kernel(const float* __restrict__ P, const float* __restrict__ bias,
                      const float* __restrict__ R, const float* __restrict__ gam,
                      const float* __restrict__ bet, float* __restrict__ Y, int MN)
{
    const int row = blockIdx.x;
    const int t = threadIdx.x;
    const int col = t * 4;
    const size_t i = (size_t)row * D_MODEL + col;

    float4 s = *(const float4*)(P + i);
    #pragma unroll
    for (int z = 1; z < SPLITK; z++) {
        float4 p = *(const float4*)(P + (size_t)z * MN + i);
        s.x += p.x; s.y += p.y; s.z += p.z; s.w += p.w;
    }
    float4 bv = *(const float4*)(bias + col);
    float4 rv = *(const float4*)(R + i);
    s.x += bv.x + rv.x;
    s.y += bv.y + rv.y;
    s.z += bv.z + rv.z;
    s.w += bv.w + rv.w;

    float a  = s.x + s.y + s.z + s.w;
    float q  = s.x * s.x + s.y * s.y + s.z * s.z + s.w * s.w;
    #pragma unroll
    for (int o = 16; o; o >>= 1) {
        a += __shfl_down_sync(0xffffffffu, a, o);
        q += __shfl_down_sync(0xffffffffu, q, o);
    }
    __shared__ float sm0[6], sm1[6], bcast[2];
    const int wid = t >> 5, lanei = t & 31;
    if (lanei == 0) { sm0[wid] = a; sm1[wid] = q; }
    __syncthreads();
    if (t == 0) {
        float ta = 0.0f, tq = 0.0f;
        #pragma unroll
        for (int w = 0; w < 6; w++) { ta += sm0[w]; tq += sm1[w]; }
        const float mean = ta * (1.0f / D_MODEL);
        const float var  = tq * (1.0f / D_MODEL) - mean * mean;
        bcast[0] = mean;
        bcast[1] = rsqrtf(var + 1e-5f);
    }
    __syncthreads();
    const float mean = bcast[0], inv = bcast[1];

    float4 gv = *(const float4*)(gam + col);
    float4 ev = *(const float4*)(bet + col);
    float4 y;
    y.x = (s.x - mean) * inv * gv.x + ev.x;
    y.y = (s.y - mean) * inv * gv.y + ev.y;
    y.z = (s.z - mean) * inv * gv.z + ev.z;
    y.w = (s.w - mean) * inv * gv.w + ev.w;
    *(float4*)(Y + i) = y;
}

// ---------------- relative-position bias MLP ----------------
__global__ __launch_bounds__(128)
void bias_kernel(const float* __restrict__ sx, const float* __restrict__ sy,
                 const float* __restrict__ P1, const float* __restrict__ pb1,
                 const float* __restrict__ P2, const float* __restrict__ pb2,
                 float* __restrict__ gbias)
{
    __shared__ float sP1[64], spb1[32], sP2[384], spb2[12];
    const int tid = threadIdx.x;
    if (tid < 64) sP1[tid] = P1[tid];
    if (tid < 32) spb1[tid] = pb1[tid];
    if (tid < 12) spb2[tid] = pb2[tid];
    for (int i = tid; i < 384; i += 128) sP2[i] = P2[i];
    __syncthreads();

    const int k = blockIdx.x * 128 + tid;
    const int q = blockIdx.y;
    const int b = blockIdx.z;

    const float xq = sx[b * NL + q], yq = sy[b * NL + q];
    float rx = fminf(fmaxf(xq - sx[b * NL + k], -1000.0f), 1000.0f) * 0.001f;
    float ry = fminf(fmaxf(yq - sy[b * NL + k], -1000.0f), 1000.0f) * 0.001f;

    float hbuf[32];
    #pragma unroll
    for (int j = 0; j < 32; j++) {
        float v = fmaf(rx, sP1[j], fmaf(ry, sP1[32 + j], spb1[j]));
        hbuf[j] = fmaxf(v, 0.0f);
    }
    #pragma unroll
    for (int h = 0; h < NHEAD; h++) {
        float s = spb2[h];
        #pragma unroll
        for (int j = 0; j < 32; j++) s = fmaf(hbuf[j], sP2[j * NHEAD + h], s);
        gbias[((((size_t)b * NHEAD + h) << 10) + q) * NL + k] = s;
    }
}

// ---------------- flash attention: tf32 mma, cp.async double-buffered K/V ----------------
// All tiles natural layout, stride 68.
// smem float layout: Q | K0 | K1 | V0 | V1 | S    (6 x 64x68)
#define AST 68
#define ATILE (64*AST)
#define ATTN_SMEM (6 * ATILE * 4)

__global__ __launch_bounds__(256, 2)
void attn_kernel(const float* __restrict__ Qg, const float* __restrict__ Kg,
                 const float* __restrict__ Vg, const float* __restrict__ biasg,
                 float* __restrict__ Og)
{
    extern __shared__ float smem[];
    const uint32_t smem_u32 = (uint32_t)__cvta_generic_to_shared(smem);
    float* Qs = smem;
    float* Ss = smem + 5 * ATILE;
    __shared__ float m_s[64], l_s[64], cf_s[64];

    const int b = blockIdx.z, h = blockIdx.y, q0 = blockIdx.x * 64;
    const int bh = b * NHEAD + h;
    const int tid = threadIdx.x;
    const int lane = tid & 31, warp = tid >> 5;
    const int wm = warp >> 1, wn = warp & 1;      // 4(m) x 2(n)
    const int frow = lane >> 2, fcol = lane & 3;

    // loader mapping: row lr = tid>>2 (0..63), 16-col chunk ld4 = (tid&3)*16
    const int lr = tid >> 2, ld4 = (tid & 3) * 16;

    // prologue: Q + K0/V0 (group 0), K1/V1 (group 1)
    {
        const float* qp = Qg + (((size_t)bh << 10) + q0 + lr) * DK + ld4;
        const uint32_t dq = smem_u32 + (uint32_t)(lr * AST + ld4) * 4;
        cp16(dq, qp); cp16(dq + 16, qp + 4); cp16(dq + 32, qp + 8); cp16(dq + 48, qp + 12);
    }
    auto load_kv = [&](int kt, int bufi) {
        const float* kp = Kg + (((size_t)bh << 10) + kt * 64 + lr) * DK + ld4;
        const float* vp = Vg + (((size_t)bh << 10) + kt * 64 + lr) * DK + ld4;
        const uint32_t dk = smem_u32 + (uint32_t)((1 + bufi) * ATILE + lr * AST + ld4) * 4;
        const uint32_t dv = smem_u32 + (uint32_t)((3 + bufi) * ATILE + lr * AST + ld4) * 4;
        cp16(dk, kp); cp16(dk + 16, kp + 4); cp16(dk + 32, kp + 8); cp16(dk + 48, kp + 12);
        cp16(dv, vp); cp16(dv + 16, vp + 4); cp16(dv + 32, vp + 8); cp16(dv + 48, vp + 12);
    };
    load_kv(0, 0); CP_COMMIT();
    load_kv(1, 1); CP_COMMIT();

    if (tid < 64) { m_s[tid] = -1e30f; l_s[tid] = 0.0f; }

    float oacc[4][4];
    #pragma unroll
    for (int i = 0; i < 4; i++)
        #pragma unroll
        for (int j = 0; j < 4; j++) oacc[i][j] = 0.0f;

    const int m = wm * 16 + frow;    // q-row this thread's fragments cover (and m+8)

    for (int kt = 0; kt < 16; kt++) {
        const int bufi = kt & 1;
        cp_wait<1>();
        __syncthreads();

        // bias register prefetch (consumed at S-write; covered by QK mma)
        float2 bvl[4][2];
        #pragma unroll
        for (int nt = 0; nt < 4; nt++) {
            const int c = wn * 32 + nt * 8 + 2 * fcol;
            bvl[nt][0] = *(const float2*)(biasg + ((((size_t)bh << 10) + q0 + m) << 10) + kt * 64 + c);
            bvl[nt][1] = *(const float2*)(biasg + ((((size_t)bh << 10) + q0 + m + 8) << 10) + kt * 64 + c);
        }

        const float* Ks = smem + (1 + bufi) * ATILE;
        const float* Vs = smem + (3 + bufi) * ATILE;

        // stage 1: S = Q K^T
        float sacc[4][4];
        #pragma unroll
        for (int i = 0; i < 4; i++)
            #pragma unroll
            for (int j = 0; j < 4; j++) sacc[i][j] = 0.0f;

        #pragma unroll
        for (int ks = 0; ks < 8; ks++) {
            const int kb = ks * 8;
            uint32_t aF[4];
            aF[0] = __float_as_uint(Qs[m * AST + kb + fcol]);
            aF[1] = __float_as_uint(Qs[(m + 8) * AST + kb + fcol]);
            aF[2] = __float_as_uint(Qs[m * AST + kb + fcol + 4]);
            aF[3] = __float_as_uint(Qs[(m + 8) * AST + kb + fcol + 4]);
            #pragma unroll
            for (int nt = 0; nt < 4; nt++) {
                const int n = wn * 32 + nt * 8 + frow;
                uint32_t bF[2];
                bF[0] = __float_as_uint(Ks[n * AST + kb + fcol]);
                bF[1] = __float_as_uint(Ks[n * AST + kb + fcol + 4]);
                mma_tf32(sacc[nt], aF, bF);
            }
        }

        // S + bias -> smem
        #pragma unroll
        for (int nt = 0; nt < 4; nt++) {
            const int c = wn * 32 + nt * 8 + 2 * fcol;
            Ss[m * AST + c]           = sacc[nt][0] + bvl[nt][0].x;
            Ss[m * AST + c + 1]       = sacc[nt][1] + bvl[nt][0].y;
            Ss[(m + 8) * AST + c]     = sacc[nt][2] + bvl[nt][1].x;
            Ss[(m + 8) * AST + c + 1] = sacc[nt][3] + bvl[nt][1].y;
        }
        __syncthreads();

        // stage 2: online softmax, 4 threads/row
        {
            const int r = tid >> 2;
            float* srow = &Ss[r * AST + (tid & 3) * 16];
            const float mold = m_s[r];
            float mx = -1e30f;
            #pragma unroll
            for (int c = 0; c < 16; c++) mx = fmaxf(mx, srow[c]);
            mx = fmaxf(mx, __shfl_xor_sync(0xffffffffu, mx, 1));
            mx = fmaxf(mx, __shfl_xor_sync(0xffffffffu, mx, 2));
            mx = fmaxf(mx, mold);
            float sum = 0.0f;
            #pragma unroll
            for (int c = 0; c < 16; c++) {
                float p = tf32f(fast_exp(srow[c] - mx));
                srow[c] = p;
                sum += p;
            }
            sum += __shfl_xor_sync(0xffffffffu, sum, 1);
            sum += __shfl_xor_sync(0xffffffffu, sum, 2);
            if ((tid & 3) == 0) {
                float cf = fast_exp(mold - mx);
                l_s[r] = l_s[r] * cf + sum;
                m_s[r] = mx;
                cf_s[r] = cf;
            }
        }
        __syncthreads();

        // stage 3: rescale + O += P @ V
        {
            const float cf0 = cf_s[m], cf1 = cf_s[m + 8];
            #pragma unroll
            for (int nt = 0; nt < 4; nt++) {
                oacc[nt][0] *= cf0; oacc[nt][1] *= cf0;
                oacc[nt][2] *= cf1; oacc[nt][3] *= cf1;
            }
        }
        #pragma unroll
        for (int ks = 0; ks < 8; ks++) {
            const int kb = ks * 8;
            uint32_t aF[4];
            aF[0] = __float_as_uint(Ss[m * AST + kb + fcol]);
            aF[1] = __float_as_uint(Ss[(m + 8) * AST + kb + fcol]);
            aF[2] = __float_as_uint(Ss[m * AST + kb + fcol + 4]);
            aF[3] = __float_as_uint(Ss[(m + 8) * AST + kb + fcol + 4]);
            #pragma unroll
            for (int nt = 0; nt < 4; nt++) {
                const int n = wn * 32 + nt * 8 + frow;
                uint32_t bF[2];
                bF[0] = __float_as_uint(Vs[(kb + fcol) * AST + n]);
                bF[1] = __float_as_uint(Vs[(kb + fcol + 4) * AST + n]);
                mma_tf32(oacc[nt], aF, bF);
            }
        }
        __syncthreads();   // all reads of K/V[bufi] and Ss done before refill

        if (kt + 2 < 16) load_kv(kt + 2, bufi);
        CP_COMMIT();
    }

    // epilogue: O[b, q, h*64 + d] = oacc / l
    {
        const float inv0 = 1.0f / l_s[m], inv1 = 1.0f / l_s[m + 8];
        #pragma unroll
        for (int nt = 0; nt < 4; nt++) {
            const int d = wn * 32 + nt * 8 + 2 * fcol;
            float2 o0; o0.x = oacc[nt][0] * inv0; o0.y = oacc[nt][1] * inv0;
            *(float2*)&Og[((size_t)b * NL + q0 + m) * D_MODEL + h * DK + d] = o0;
            float2 o1; o1.x = oacc[nt][2] * inv1; o1.y = oacc[nt][3] * inv1;
            *(float2*)&Og[((size_t)b * NL + q0 + m + 8) * D_MODEL + h * DK + d] = o1;
        }
    }
}

// ---------------- launch ----------------
extern "C" void kernel_launch(void* const* d_in, const int* in_sizes, int n_in,
                              void* d_out, int out_size)
{
    const float* src = (const float*)d_in[0];
    const float* sx  = (const float*)d_in[1];
    const float* sy  = (const float*)d_in[2];
    const float* Wq  = (const float*)d_in[3];
    const float* bq  = (const float*)d_in[4];
    const float* Wk  = (const float*)d_in[5];
    const float* bk  = (const float*)d_in[6];
    const float* Wv  = (const float*)d_in[7];
    const float* bv  = (const float*)d_in[8];
    const float* Wo  = (const float*)d_in[9];
    const float* bo  = (const float*)d_in[10];
    const float* P1  = (const float*)d_in[11];
    const float* pb1 = (const float*)d_in[12];
    const float* P2  = (const float*)d_in[13];
    const float* pb2 = (const float*)d_in[14];
    const float* W1  = (const float*)d_in[15];
    const float* b1  = (const float*)d_in[16];
    const float* W2  = (const float*)d_in[17];
    const float* b2  = (const float*)d_in[18];
    const float* g1  = (const float*)d_in[19];
    const float* be1 = (const float*)d_in[20];
    const float* g2  = (const float*)d_in[21];
    const float* be2 = (const float*)d_in[22];

    float* scratch = nullptr;
    cudaGetSymbolAddress((void**)&scratch, g_scratch);
    float* Q    = scratch + OFF_Q;
    float* K    = scratch + OFF_K;
    float* V    = scratch + OFF_V;
    float* Bias = scratch + OFF_BIAS;
    float* AO   = scratch + OFF_AO;
    float* X    = scratch + OFF_X;
    float* Hb   = scratch + OFF_H;
    float* PART = scratch + OFF_PART;

    cudaFuncSetAttribute(attn_kernel, cudaFuncAttributeMaxDynamicSharedMemorySize, ATTN_SMEM);
    cudaFuncSetAttribute(tgemm_kernel<MODE_QKV>, cudaFuncAttributeMaxDynamicSharedMemorySize, TG_SMEM);
    cudaFuncSetAttribute(tgemm_kernel<MODE_PART>, cudaFuncAttributeMaxDynamicSharedMemorySize, TG_SMEM);
    cudaFuncSetAttribute(tgemm_kernel<MODE_BIAS_RELU>, cudaFuncAttributeMaxDynamicSharedMemorySize, TG_SMEM);

    const int MN = MTOT * D_MODEL;

    // 1. fused QKV projection (tf32 tensor) -> (b,h,l,dk), Q pre-scaled
    tgemm_kernel<MODE_QKV><<<dim3(2304 / BN, MTOT / BM), 256, TG_SMEM>>>(
        src, Wq, Wk, Wv, bq, bk, bv, nullptr, Q, K, V, MTOT, 2304, D_MODEL, D_MODEL);

    // 2. relative-position bias
    bias_kernel<<<dim3(NL / 128, NL, NB), 128>>>(sx, sy, P1, pb1, P2, pb2, Bias);

    // 3. flash attention (tf32 tensor, cp.async pipelined)
    attn_kernel<<<dim3(NL / 64, NHEAD, NB), 256, ATTN_SMEM>>>(Q, K, V, Bias, AO);

    // 4. output projection split-K=4 + fused reduce+bias+residual+LN1 -> X
    tgemm_kernel<MODE_PART><<<dim3(D_MODEL / BN, MTOT / BM, 4), 256, TG_SMEM>>>(
        AO, Wo, nullptr, nullptr, nullptr, nullptr, nullptr, nullptr,
        PART, nullptr, nullptr, MTOT, D_MODEL, 192, D_MODEL);
    reduce_ln_kernel<4><<<MTOT, 192>>>(PART, bo, src, g1, be1, X, MN);

    // 5. FFN up + ReLU
    tgemm_kernel<MODE_BIAS_RELU><<<dim3(FF / BN, MTOT / BM), 256, TG_SMEM>>>(
        X, W1, nullptr, nullptr, b1, nullptr, nullptr, nullptr, Hb, nullptr, nullptr,
        MTOT, FF, D_MODEL, D_MODEL);

    // 6. FFN down split-K=8 + fused reduce+bias+residual+LN2 -> out
    tgemm_kernel<MODE_PART><<<dim3(D_MODEL / BN, MTOT / BM, 8), 256, TG_SMEM>>>(
        Hb, W2, nullptr, nullptr, nullptr, nullptr, nullptr, nullptr,
        PART, nullptr, nullptr, MTOT, D_MODEL, 384, FF);
    reduce_ln_kernel<8><<<MTOT, 192>>>(PART, b2, X, g2, be2, (float*)d_out, MN);
}